// round 11
// baseline (speedup 1.0000x reference)
#include <cuda_runtime.h>
#include <cuda_bf16.h>
#include <math.h>
#include <stdint.h>

// Problem constants
#define B_SZ     4
#define C_DIM    256
#define T_LEN    4096
#define FF_DIM   1024
#define NLAYERS  2
#define CHUNK    128
#define S_LEN    384          // 3*CHUNK
#define NW       32           // T/CHUNK
#define NSEQ     128          // B*NW
#define M_TOTAL  49152        // NSEQ*S_LEN
#define NHEADS   8
#define DH       32
#define EPS      1e-5f

typedef __nv_bfloat16  bf16;
typedef __nv_bfloat162 bf162;

// ---------------------------------------------------------------------------
// Device scratch. Residual stream fp32 with bf16 mirrors; big intermediates bf16.
// ---------------------------------------------------------------------------
__device__ float g_bufA [M_TOTAL * C_DIM];
__device__ float g_bufB [M_TOTAL * C_DIM];
__device__ bf16  g_bufAh[M_TOTAL * C_DIM];
__device__ bf16  g_bufBh[M_TOTAL * C_DIM];
__device__ bf16  g_qkv  [M_TOTAL * 768];
__device__ bf16  g_att  [M_TOTAL * C_DIM];
__device__ bf16  g_h    [M_TOTAL * FF_DIM];
__device__ bf16  g_wbf  [2097152];           // all weights, bf16

// bf16 weight buffer offsets (elems)
#define OFF_SAW   0         // 2 x 196608
#define OFF_SAOW  393216    // 2 x 65536
#define OFF_CAW   524288    // 2 x 196608
#define OFF_CAOW  917504    // 2 x 65536
#define OFF_W1    1048576   // 2 x 262144
#define OFF_W2    1572864   // 2 x 262144

// ---------------------------------------------------------------------------
// helpers
// ---------------------------------------------------------------------------
__device__ __forceinline__ uint32_t packbf(float x, float y)
{
    bf162 h = __floats2bfloat162_rn(x, y);
    return *(uint32_t*)&h;
}

__device__ __forceinline__ void mma_bf16(float* c, const uint32_t* a, const uint32_t* b)
{
    asm volatile("mma.sync.aligned.m16n8k16.row.col.f32.bf16.bf16.f32 "
                 "{%0,%1,%2,%3}, {%4,%5,%6,%7}, {%8,%9}, {%0,%1,%2,%3};"
                 : "+f"(c[0]), "+f"(c[1]), "+f"(c[2]), "+f"(c[3])
                 : "r"(a[0]), "r"(a[1]), "r"(a[2]), "r"(a[3]),
                   "r"(b[0]), "r"(b[1]));
}

__device__ __forceinline__ void ldsm_x4b(uint32_t* d, const bf16* p)
{
    uint32_t a = (uint32_t)__cvta_generic_to_shared(p);
    asm volatile("ldmatrix.sync.aligned.m8n8.x4.shared.b16 {%0,%1,%2,%3}, [%4];"
                 : "=r"(d[0]), "=r"(d[1]), "=r"(d[2]), "=r"(d[3]) : "r"(a));
}

// ---------------------------------------------------------------------------
// Weight fp32 -> bf16 conversion
// ---------------------------------------------------------------------------
__global__ void convert_w_kernel(const float* __restrict__ src, bf16* __restrict__ dst, int n4)
{
    int i = blockIdx.x * blockDim.x + threadIdx.x;
    if (i < n4) {
        float4 v = ((const float4*)src)[i];
        bf162 a = __floats2bfloat162_rn(v.x, v.y);
        bf162 b = __floats2bfloat162_rn(v.z, v.w);
        ((bf162*)dst)[2 * i]     = a;
        ((bf162*)dst)[2 * i + 1] = b;
    }
}

// ---------------------------------------------------------------------------
// build_x: window gather + PE; writes fp32 + bf16 mirror
// ---------------------------------------------------------------------------
__global__ void build_x_kernel(const float* __restrict__ mem, float* __restrict__ x,
                               bf16* __restrict__ xh)
{
    __shared__ float tile[32][33];
    int p0 = blockIdx.x * 32, c0 = blockIdx.y * 32, seq = blockIdx.z;
    int b = seq >> 5, w = seq & 31;
    int tx = threadIdx.x, ty = threadIdx.y;
    int t_off = w * CHUNK + p0 - CHUNK;
    #pragma unroll
    for (int i = ty; i < 32; i += 8) {
        int tpos = t_off + tx;
        float v = 0.f;
        if (tpos >= 0 && tpos < T_LEN)
            v = mem[((size_t)b * C_DIM + c0 + i) * T_LEN + tpos];
        tile[i][tx] = v;
    }
    __syncthreads();
    #pragma unroll
    for (int i = ty; i < 32; i += 8) {
        int p = p0 + i;
        int c = c0 + tx;
        int j = c >> 1;
        float dv  = __expf((float)(2 * j) * (-9.210340371976184f / (float)C_DIM));
        float ang = (float)p * dv;
        float pe  = (c & 1) ? cosf(ang) : sinf(ang);
        float val = tile[tx][i] + pe;
        size_t idx = ((size_t)seq * S_LEN + p) * C_DIM + c;
        x[idx]  = val;
        xh[idx] = __float2bfloat16_rn(val);
    }
}

// ---------------------------------------------------------------------------
// bf16 GEMM (m16n8k16).  C[m,n] = sum_k A[m,k]*W[n,k] + bias[n] (+ReLU)
// Block 128x128, BK=32, 8 warps 2x4, warp 64x32. smem stride 40 bf16.
// ---------------------------------------------------------------------------
#define GSTR 40
template<int CBF16>
__global__ __launch_bounds__(256, 2)
void bgemm_t(const bf16* __restrict__ A, int lda,
             const bf16* __restrict__ W, int ldw,
             const float* __restrict__ bias,
             void* __restrict__ Cv, int ldc,
             int K, int doRelu)
{
    __shared__ __align__(16) bf16 As[2][128 * GSTR];
    __shared__ __align__(16) bf16 Bs[2][128 * GSTR];

    int tid  = threadIdx.x;
    int lane = tid & 31;
    int warp = tid >> 5;
    int wm = warp & 1;
    int wn = warp >> 1;
    int bm = blockIdx.y, bn = blockIdx.x;
    int r  = lane >> 2;
    int cc = lane & 3;

    int srow = tid & 127;
    int soff = (tid >> 7) * 16;
    const bf16* Ap = A + (size_t)(bm * 128 + srow) * lda + soff;
    const bf16* Wp = W + (size_t)(bn * 128 + srow) * ldw + soff;

    int a_row = wm * 64 + (lane & 15);
    int a_col = ((lane >> 4) & 1) * 8;
    int b_row = wn * 32 + (lane >> 4) * 8 + (lane & 7);
    int b_col = ((lane >> 3) & 1) * 8;

    float acc[4][4][4];
    #pragma unroll
    for (int i = 0; i < 4; i++)
        #pragma unroll
        for (int j = 0; j < 4; j++)
            #pragma unroll
            for (int q = 0; q < 4; q++) acc[i][j][q] = 0.f;

    {
        uint4 a0 = *(const uint4*)(Ap);
        uint4 a1 = *(const uint4*)(Ap + 8);
        uint4 b0 = *(const uint4*)(Wp);
        uint4 b1 = *(const uint4*)(Wp + 8);
        *(uint4*)&As[0][srow * GSTR + soff]     = a0;
        *(uint4*)&As[0][srow * GSTR + soff + 8] = a1;
        *(uint4*)&Bs[0][srow * GSTR + soff]     = b0;
        *(uint4*)&Bs[0][srow * GSTR + soff + 8] = b1;
    }
    __syncthreads();

    int niter = K >> 5;
    uint4 pa0, pa1, pb0, pb1;
    for (int it = 0; it < niter; it++) {
        int cur = it & 1;
        if (it + 1 < niter) {
            pa0 = *(const uint4*)(Ap + (it + 1) * 32);
            pa1 = *(const uint4*)(Ap + (it + 1) * 32 + 8);
            pb0 = *(const uint4*)(Wp + (it + 1) * 32);
            pb1 = *(const uint4*)(Wp + (it + 1) * 32 + 8);
        }

        const bf16* Ac = As[cur];
        const bf16* Bc = Bs[cur];
        #pragma unroll
        for (int kb = 0; kb < 2; kb++) {
            uint32_t af[4][4];
            uint32_t bfr[4][2];
            #pragma unroll
            for (int mt = 0; mt < 4; mt++)
                ldsm_x4b(af[mt], Ac + (a_row + mt * 16) * GSTR + kb * 16 + a_col);
            #pragma unroll
            for (int np = 0; np < 2; np++) {
                uint32_t t4[4];
                ldsm_x4b(t4, Bc + (b_row + np * 16) * GSTR + kb * 16 + b_col);
                bfr[2 * np][0]     = t4[0];
                bfr[2 * np][1]     = t4[1];
                bfr[2 * np + 1][0] = t4[2];
                bfr[2 * np + 1][1] = t4[3];
            }
            #pragma unroll
            for (int mt = 0; mt < 4; mt++)
                #pragma unroll
                for (int nt = 0; nt < 4; nt++)
                    mma_bf16(acc[mt][nt], af[mt], bfr[nt]);
        }

        if (it + 1 < niter) {
            int nxt = cur ^ 1;
            *(uint4*)&As[nxt][srow * GSTR + soff]     = pa0;
            *(uint4*)&As[nxt][srow * GSTR + soff + 8] = pa1;
            *(uint4*)&Bs[nxt][srow * GSTR + soff]     = pb0;
            *(uint4*)&Bs[nxt][srow * GSTR + soff + 8] = pb1;
        }
        __syncthreads();
    }

    int c2 = cc * 2;
    #pragma unroll
    for (int mt = 0; mt < 4; mt++) {
        int row0 = bm * 128 + wm * 64 + mt * 16 + r;
        #pragma unroll
        for (int nt = 0; nt < 4; nt++) {
            int col = bn * 128 + wn * 32 + nt * 8 + c2;
            float bx = bias[col], by = bias[col + 1];
            float2 v0, v1;
            v0.x = acc[mt][nt][0] + bx; v0.y = acc[mt][nt][1] + by;
            v1.x = acc[mt][nt][2] + bx; v1.y = acc[mt][nt][3] + by;
            if (doRelu) {
                v0.x = fmaxf(v0.x, 0.f); v0.y = fmaxf(v0.y, 0.f);
                v1.x = fmaxf(v1.x, 0.f); v1.y = fmaxf(v1.y, 0.f);
            }
            if (CBF16) {
                bf16* Cp = (bf16*)Cv;
                *(bf162*)(Cp + (size_t)row0 * ldc + col)       = __float22bfloat162_rn(v0);
                *(bf162*)(Cp + (size_t)(row0 + 8) * ldc + col) = __float22bfloat162_rn(v1);
            } else {
                float* Cp = (float*)Cv;
                *(float2*)(Cp + (size_t)row0 * ldc + col)       = v0;
                *(float2*)(Cp + (size_t)(row0 + 8) * ldc + col) = v1;
            }
        }
    }
}

// ---------------------------------------------------------------------------
// Fused bf16 GEMM (N=256 full row) + bias + residual add + LayerNorm.
//   v[m,:] = GEMM(A,W)[m,:] + bias + xres[m,:]
//   out[m,:] = (v - mean)*rsqrt(var+eps)*g + b   (fp32 + bf16 mirror)
// Block tile 64x256, BK=32, 8 warps (2M x 4N), warp 32x64.
// Dynamic smem: As 2x64x40 + Bs 2x256x40 bf16 = 51200 B.
// ---------------------------------------------------------------------------
__global__ __launch_bounds__(256, 2)
void bgemm_ln(const bf16* __restrict__ A, int lda,
              const bf16* __restrict__ W,          // 256 x K
              const float* __restrict__ bias,
              const float* __restrict__ xres,
              const float* __restrict__ g, const float* __restrict__ b,
              float* __restrict__ out, bf16* __restrict__ outh,
              int K)
{
    extern __shared__ __align__(16) char dynsm[];
    bf16* AsBase = (bf16*)dynsm;               // 2 * 64*40
    bf16* BsBase = AsBase + 2 * 64 * 40;       // 2 * 256*40
    __shared__ float redS[64][4];
    __shared__ float redQ[64][4];

    int tid  = threadIdx.x;
    int lane = tid & 31;
    int warp = tid >> 5;
    int wm = warp & 1;      // 0..1 (32 rows each)
    int wn = warp >> 1;     // 0..3 (64 cols each)
    int bm = blockIdx.x;
    int r  = lane >> 2;
    int cc = lane & 3;

    // staging: A row = tid>>2 (0..63), chunk = tid&3 (8 bf16); B row = tid, 4 chunks
    int arow_s = tid >> 2;
    int achk   = (tid & 3) * 8;
    const bf16* Ap = A + (size_t)(bm * 64 + arow_s) * lda + achk;
    const bf16* Wp = W + (size_t)tid * K;

    int a_row = wm * 32 + (lane & 15);
    int a_col = ((lane >> 4) & 1) * 8;
    int b_row = wn * 64 + (lane >> 4) * 8 + (lane & 7);
    int b_col = ((lane >> 3) & 1) * 8;

    float acc[2][8][4];
    #pragma unroll
    for (int i = 0; i < 2; i++)
        #pragma unroll
        for (int j = 0; j < 8; j++)
            #pragma unroll
            for (int q = 0; q < 4; q++) acc[i][j][q] = 0.f;

    // prologue
    {
        bf16* As = AsBase;
        bf16* Bs = BsBase;
        *(uint4*)&As[arow_s * 40 + achk] = *(const uint4*)(Ap);
        #pragma unroll
        for (int c = 0; c < 4; c++)
            *(uint4*)&Bs[tid * 40 + c * 8] = *(const uint4*)(Wp + c * 8);
    }
    __syncthreads();

    int niter = K >> 5;
    uint4 pa, pb[4];
    for (int it = 0; it < niter; it++) {
        int cur = it & 1;
        if (it + 1 < niter) {
            pa = *(const uint4*)(Ap + (it + 1) * 32);
            #pragma unroll
            for (int c = 0; c < 4; c++)
                pb[c] = *(const uint4*)(Wp + (it + 1) * 32 + c * 8);
        }

        const bf16* Ac = AsBase + cur * 64 * 40;
        const bf16* Bc = BsBase + cur * 256 * 40;
        #pragma unroll
        for (int kb = 0; kb < 2; kb++) {
            uint32_t af[2][4];
            uint32_t bfr[8][2];
            #pragma unroll
            for (int mt = 0; mt < 2; mt++)
                ldsm_x4b(af[mt], Ac + (a_row + mt * 16) * 40 + kb * 16 + a_col);
            #pragma unroll
            for (int np = 0; np < 4; np++) {
                uint32_t t4[4];
                ldsm_x4b(t4, Bc + (b_row + np * 16) * 40 + kb * 16 + b_col);
                bfr[2 * np][0]     = t4[0];
                bfr[2 * np][1]     = t4[1];
                bfr[2 * np + 1][0] = t4[2];
                bfr[2 * np + 1][1] = t4[3];
            }
            #pragma unroll
            for (int mt = 0; mt < 2; mt++)
                #pragma unroll
                for (int nt = 0; nt < 8; nt++)
                    mma_bf16(acc[mt][nt], af[mt], bfr[nt]);
        }

        if (it + 1 < niter) {
            int nxt = cur ^ 1;
            bf16* As = AsBase + nxt * 64 * 40;
            bf16* Bs = BsBase + nxt * 256 * 40;
            *(uint4*)&As[arow_s * 40 + achk] = pa;
            #pragma unroll
            for (int c = 0; c < 4; c++)
                *(uint4*)&Bs[tid * 40 + c * 8] = pb[c];
        }
        __syncthreads();
    }

    // ---- epilogue: bias + residual, row stats ----
    int c2 = cc * 2;
    float s[2][2], q2[2][2];
    #pragma unroll
    for (int mt = 0; mt < 2; mt++) { s[mt][0]=0.f; s[mt][1]=0.f; q2[mt][0]=0.f; q2[mt][1]=0.f; }

    #pragma unroll
    for (int mt = 0; mt < 2; mt++) {
        int row0 = bm * 64 + wm * 32 + mt * 16 + r;
        #pragma unroll
        for (int nt = 0; nt < 8; nt++) {
            int col = wn * 64 + nt * 8 + c2;
            float bx = bias[col], by = bias[col + 1];
            float2 x0 = *(const float2*)(xres + (size_t)row0 * C_DIM + col);
            float2 x1 = *(const float2*)(xres + (size_t)(row0 + 8) * C_DIM + col);
            float v0 = acc[mt][nt][0] + bx + x0.x;
            float v1 = acc[mt][nt][1] + by + x0.y;
            float v2 = acc[mt][nt][2] + bx + x1.x;
            float v3 = acc[mt][nt][3] + by + x1.y;
            acc[mt][nt][0] = v0; acc[mt][nt][1] = v1;
            acc[mt][nt][2] = v2; acc[mt][nt][3] = v3;
            s[mt][0]  += v0 + v1;
            s[mt][1]  += v2 + v3;
            q2[mt][0] += v0 * v0 + v1 * v1;
            q2[mt][1] += v2 * v2 + v3 * v3;
        }
    }
    // quad reduce (over cc) -> per-(row, n-warp) partial over 64 cols
    #pragma unroll
    for (int mt = 0; mt < 2; mt++)
        #pragma unroll
        for (int h = 0; h < 2; h++) {
            float sv = s[mt][h], qv = q2[mt][h];
            sv += __shfl_xor_sync(0xFFFFFFFFu, sv, 1);
            sv += __shfl_xor_sync(0xFFFFFFFFu, sv, 2);
            qv += __shfl_xor_sync(0xFFFFFFFFu, qv, 1);
            qv += __shfl_xor_sync(0xFFFFFFFFu, qv, 2);
            if (cc == 0) {
                int lrow = wm * 32 + mt * 16 + r + h * 8;
                redS[lrow][wn] = sv;
                redQ[lrow][wn] = qv;
            }
        }
    __syncthreads();

    float mean[2][2], rstd[2][2];
    #pragma unroll
    for (int mt = 0; mt < 2; mt++)
        #pragma unroll
        for (int h = 0; h < 2; h++) {
            int lrow = wm * 32 + mt * 16 + r + h * 8;
            float ts = redS[lrow][0] + redS[lrow][1] + redS[lrow][2] + redS[lrow][3];
            float tq = redQ[lrow][0] + redQ[lrow][1] + redQ[lrow][2] + redQ[lrow][3];
            float m  = ts * (1.f / C_DIM);
            float vr = tq * (1.f / C_DIM) - m * m;
            mean[mt][h] = m;
            rstd[mt][h] = rsqrtf(vr + EPS);
        }

    #pragma unroll
    for (int mt = 0; mt < 2; mt++) {
        int row0 = bm * 64 + wm * 32 + mt * 16 + r;
        #pragma unroll
        for (int nt = 0; nt < 8; nt++) {
            int col = wn * 64 + nt * 8 + c2;
            float gx = g[col], gy = g[col + 1];
            float bx = b[col], by = b[col + 1];
            float2 o0, o1;
            o0.x = (acc[mt][nt][0] - mean[mt][0]) * rstd[mt][0] * gx + bx;
            o0.y = (acc[mt][nt][1] - mean[mt][0]) * rstd[mt][0] * gy + by;
            o1.x = (acc[mt][nt][2] - mean[mt][1]) * rstd[mt][1] * gx + bx;
            o1.y = (acc[mt][nt][3] - mean[mt][1]) * rstd[mt][1] * gy + by;
            *(float2*)(out + (size_t)row0 * C_DIM + col)       = o0;
            *(float2*)(out + (size_t)(row0 + 8) * C_DIM + col) = o1;
            *(bf162*)(outh + (size_t)row0 * C_DIM + col)       = __float22bfloat162_rn(o0);
            *(bf162*)(outh + (size_t)(row0 + 8) * C_DIM + col) = __float22bfloat162_rn(o1);
        }
    }
}

// ---------------------------------------------------------------------------
// bf16 MMA flash attention (unchanged from R9).
// ---------------------------------------------------------------------------
#define KSB 40
#define VSB 72

__global__ __launch_bounds__(128, 3)
void attn_bf16_kernel(const bf16* __restrict__ qkv, bf16* __restrict__ att)
{
    __shared__ __align__(16) bf16 Ks[64 * KSB];
    __shared__ __align__(16) bf16 Vs[32 * VSB];

    int tid  = threadIdx.x;
    int lane = tid & 31, warp = tid >> 5;
    int r = lane >> 2, cc = lane & 3;
    int seq = blockIdx.y, h = blockIdx.z;
    int qbase = blockIdx.x * 128 + warp * 32;
    const bf16* base = qkv + (size_t)seq * S_LEN * 768;

    int brow = (lane & 7) + ((lane >> 4) & 1) * 8;
    int bcol = ((lane >> 3) & 1) * 8;

    uint32_t qa[2][2][4];
    #pragma unroll
    for (int mt = 0; mt < 2; mt++) {
        const bf16* q0 = base + (size_t)(qbase + mt * 16 + r) * 768 + h * DH;
        const bf16* q1 = q0 + 8 * 768;
        const float sc = 0.17677669529663687f;
        #pragma unroll
        for (int kb = 0; kb < 2; kb++) {
            bf162 p00 = *(const bf162*)(q0 + kb * 16 + 2 * cc);
            bf162 p01 = *(const bf162*)(q0 + kb * 16 + 2 * cc + 8);
            bf162 p10 = *(const bf162*)(q1 + kb * 16 + 2 * cc);
            bf162 p11 = *(const bf162*)(q1 + kb * 16 + 2 * cc + 8);
            float2 f;
            f = __bfloat1622float2(p00); qa[mt][kb][0] = packbf(f.x * sc, f.y * sc);
            f = __bfloat1622float2(p10); qa[mt][kb][1] = packbf(f.x * sc, f.y * sc);
            f = __bfloat1622float2(p01); qa[mt][kb][2] = packbf(f.x * sc, f.y * sc);
            f = __bfloat1622float2(p11); qa[mt][kb][3] = packbf(f.x * sc, f.y * sc);
        }
    }

    float lrun[2][2], oacc[2][4][4];
    #pragma unroll
    for (int mt = 0; mt < 2; mt++) {
        lrun[mt][0] = 0.f; lrun[mt][1] = 0.f;
        #pragma unroll
        for (int nt = 0; nt < 4; nt++)
            #pragma unroll
            for (int q = 0; q < 4; q++) oacc[mt][nt][q] = 0.f;
    }

    for (int kv0 = 0; kv0 < S_LEN; kv0 += 64) {
        __syncthreads();
        {
            int key = tid & 63, ch = tid >> 6;
            const bf16* src = base + (size_t)(kv0 + key) * 768 + 256 + h * DH + ch * 16;
            uint4 k0 = *(const uint4*)src;
            uint4 k1 = *(const uint4*)(src + 8);
            *(uint4*)&Ks[key * KSB + ch * 16]     = k0;
            *(uint4*)&Ks[key * KSB + ch * 16 + 8] = k1;
        }
        {
            int kp = tid & 31, oct = tid >> 5;
            const bf16* v0 = base + (size_t)(kv0 + 2 * kp) * 768 + 512 + h * DH + oct * 8;
            uint4 ra = *(const uint4*)v0;
            uint4 rb = *(const uint4*)(v0 + 768);
            const bf16* va = (const bf16*)&ra;
            const bf16* vb = (const bf16*)&rb;
            #pragma unroll
            for (int d = 0; d < 8; d++) {
                bf162 pr;
                pr.x = va[d]; pr.y = vb[d];
                *(bf162*)&Vs[(oct * 8 + d) * VSB + 2 * kp] = pr;
            }
        }
        __syncthreads();

        float sacc[2][8][4];
        #pragma unroll
        for (int mt = 0; mt < 2; mt++)
            #pragma unroll
            for (int nt = 0; nt < 8; nt++)
                #pragma unroll
                for (int q = 0; q < 4; q++) sacc[mt][nt][q] = 0.f;

        #pragma unroll
        for (int kb = 0; kb < 2; kb++) {
            #pragma unroll
            for (int kq = 0; kq < 4; kq++) {
                uint32_t t4[4];
                ldsm_x4b(t4, Ks + (kq * 16 + brow) * KSB + kb * 16 + bcol);
                #pragma unroll
                for (int mt = 0; mt < 2; mt++) {
                    mma_bf16(sacc[mt][2 * kq],     qa[mt][kb], t4);
                    mma_bf16(sacc[mt][2 * kq + 1], qa[mt][kb], t4 + 2);
                }
            }
        }

        #pragma unroll
        for (int kg = 0; kg < 4; kg++) {
            uint32_t bv[4][2];
            #pragma unroll
            for (int np = 0; np < 2; np++) {
                uint32_t t4[4];
                ldsm_x4b(t4, Vs + (np * 16 + brow) * VSB + kg * 16 + bcol);
                bv[2 * np][0]     = t4[0];
                bv[2 * np][1]     = t4[1];
                bv[2 * np + 1][0] = t4[2];
                bv[2 * np + 1][1] = t4[3];
            }
            #pragma unroll
            for (int mt = 0; mt < 2; mt++) {
                float e0 = __expf(sacc[mt][2 * kg][0]);
                float e1 = __expf(sacc[mt][2 * kg][1]);
                float e2 = __expf(sacc[mt][2 * kg][2]);
                float e3 = __expf(sacc[mt][2 * kg][3]);
                float e4 = __expf(sacc[mt][2 * kg + 1][0]);
                float e5 = __expf(sacc[mt][2 * kg + 1][1]);
                float e6 = __expf(sacc[mt][2 * kg + 1][2]);
                float e7 = __expf(sacc[mt][2 * kg + 1][3]);
                lrun[mt][0] += e0 + e1 + e4 + e5;
                lrun[mt][1] += e2 + e3 + e6 + e7;
                uint32_t af[4];
                af[0] = packbf(e0, e1);
                af[1] = packbf(e2, e3);
                af[2] = packbf(e4, e5);
                af[3] = packbf(e6, e7);
                #pragma unroll
                for (int nt = 0; nt < 4; nt++)
                    mma_bf16(oacc[mt][nt], af, bv[nt]);
            }
        }
    }

    #pragma unroll
    for (int mt = 0; mt < 2; mt++) {
        float l0 = lrun[mt][0];
        l0 += __shfl_xor_sync(0xFFFFFFFFu, l0, 1);
        l0 += __shfl_xor_sync(0xFFFFFFFFu, l0, 2);
        float l1 = lrun[mt][1];
        l1 += __shfl_xor_sync(0xFFFFFFFFu, l1, 1);
        l1 += __shfl_xor_sync(0xFFFFFFFFu, l1, 2);
        float inv0 = 1.f / l0, inv1 = 1.f / l1;
        size_t grow = (size_t)seq * S_LEN + qbase + mt * 16 + r;
        #pragma unroll
        for (int nt = 0; nt < 4; nt++) {
            int col = h * DH + nt * 8 + 2 * cc;
            float2 v0, v1;
            v0.x = oacc[mt][nt][0] * inv0; v0.y = oacc[mt][nt][1] * inv0;
            v1.x = oacc[mt][nt][2] * inv1; v1.y = oacc[mt][nt][3] * inv1;
            *(bf162*)(att + grow * C_DIM + col)       = __float22bfloat162_rn(v0);
            *(bf162*)(att + (grow + 8) * C_DIM + col) = __float22bfloat162_rn(v1);
        }
    }
}

// ---------------------------------------------------------------------------
// Final gather
// ---------------------------------------------------------------------------
__global__ void final_out_kernel(const float* __restrict__ x, float* __restrict__ out)
{
    __shared__ float tile[32][33];
    int t0 = blockIdx.x * 32, c0 = blockIdx.y * 32, b = blockIdx.z;
    int tx = threadIdx.x, ty = threadIdx.y;
    #pragma unroll
    for (int i = ty; i < 32; i += 8) {
        int t = t0 + i;
        size_t row = (size_t)(b * NW + (t >> 7)) * S_LEN + CHUNK + (t & 127);
        tile[i][tx] = x[row * C_DIM + c0 + tx];
    }
    __syncthreads();
    #pragma unroll
    for (int i = ty; i < 32; i += 8)
        out[((size_t)b * C_DIM + c0 + i) * T_LEN + t0 + tx] = tile[tx][i];
}

// ---------------------------------------------------------------------------
// Host orchestration
// ---------------------------------------------------------------------------
extern "C" void kernel_launch(void* const* d_in, const int* in_sizes, int n_in,
                              void* d_out, int out_size)
{
    (void)in_sizes; (void)n_in; (void)out_size;
    const float* mem   = (const float*)d_in[0];
    const float* sa_w  = (const float*)d_in[1];
    const float* sa_b  = (const float*)d_in[2];
    const float* sa_ow = (const float*)d_in[3];
    const float* sa_ob = (const float*)d_in[4];
    const float* ca_w  = (const float*)d_in[5];
    const float* ca_b  = (const float*)d_in[6];
    const float* ca_ow = (const float*)d_in[7];
    const float* ca_ob = (const float*)d_in[8];
    const float* w1    = (const float*)d_in[9];
    const float* b1f   = (const float*)d_in[10];
    const float* w2    = (const float*)d_in[11];
    const float* b2f   = (const float*)d_in[12];
    const float* ln_g  = (const float*)d_in[13];
    const float* ln_b  = (const float*)d_in[14];

    float *bufA, *bufB;
    bf16 *bufAh, *bufBh, *qkv, *att, *h, *wbf;
    cudaGetSymbolAddress((void**)&bufA,  g_bufA);
    cudaGetSymbolAddress((void**)&bufB,  g_bufB);
    cudaGetSymbolAddress((void**)&bufAh, g_bufAh);
    cudaGetSymbolAddress((void**)&bufBh, g_bufBh);
    cudaGetSymbolAddress((void**)&qkv,   g_qkv);
    cudaGetSymbolAddress((void**)&att,   g_att);
    cudaGetSymbolAddress((void**)&h,     g_h);
    cudaGetSymbolAddress((void**)&wbf,   g_wbf);

    const int ln_smem = (2 * 64 * 40 + 2 * 256 * 40) * (int)sizeof(bf16);   // 51200
    cudaFuncSetAttribute(bgemm_ln, cudaFuncAttributeMaxDynamicSharedMemorySize, ln_smem);

    // weights -> bf16
    convert_w_kernel<<< 384, 256>>>(sa_w,  wbf + OFF_SAW,   98304);
    convert_w_kernel<<< 128, 256>>>(sa_ow, wbf + OFF_SAOW,  32768);
    convert_w_kernel<<< 384, 256>>>(ca_w,  wbf + OFF_CAW,   98304);
    convert_w_kernel<<< 128, 256>>>(ca_ow, wbf + OFF_CAOW,  32768);
    convert_w_kernel<<< 512, 256>>>(w1,    wbf + OFF_W1,   131072);
    convert_w_kernel<<< 512, 256>>>(w2,    wbf + OFF_W2,   131072);

    build_x_kernel<<<dim3(12, 8, NSEQ), dim3(32, 8)>>>(mem, bufA, bufAh);

    const int MB  = M_TOTAL / 128;   // 384
    const int MB2 = M_TOTAL / 64;    // 768
    dim3 attn_grid(3, NSEQ, NHEADS);

    float* LI = bufA;   bf16* LIh = bufAh;
    float* OT = bufB;   bf16* OTh = bufBh;

    for (int l = 0; l < NLAYERS; l++) {
        const bf16* w_qkv  = wbf + OFF_SAW  + (size_t)l * 196608;
        const bf16* w_saow = wbf + OFF_SAOW + (size_t)l * 65536;
        const bf16* w_caw  = wbf + OFF_CAW  + (size_t)l * 196608;
        const bf16* w_caow = wbf + OFF_CAOW + (size_t)l * 65536;
        const bf16* w_ff1  = wbf + OFF_W1   + (size_t)l * 262144;
        const bf16* w_ff2  = wbf + OFF_W2   + (size_t)l * 262144;

        // ---- self attention ----
        bgemm_t<1><<<dim3(768/128, MB), 256>>>(LIh, C_DIM, w_qkv, C_DIM,
                                               sa_b + (size_t)l*768, qkv, 768, C_DIM, 0);
        attn_bf16_kernel<<<attn_grid, 128>>>(qkv, att);
        bgemm_ln<<<MB2, 256, ln_smem>>>(att, C_DIM, w_saow,
                                        sa_ob + (size_t)l*256, LI,
                                        ln_g + (size_t)(l*3 + 0)*C_DIM,
                                        ln_b + (size_t)(l*3 + 0)*C_DIM,
                                        OT, OTh, C_DIM);

        // ---- cross attention (Q from OT=x1, K/V from LI=layer input) ----
        bgemm_t<1><<<dim3(256/128, MB), 256>>>(OTh, C_DIM, w_caw, C_DIM,
                                               ca_b + (size_t)l*768, qkv, 768, C_DIM, 0);
        bgemm_t<1><<<dim3(512/128, MB), 256>>>(LIh, C_DIM, w_caw + 256*256, C_DIM,
                                               ca_b + (size_t)l*768 + 256, qkv + 256, 768, C_DIM, 0);
        attn_bf16_kernel<<<attn_grid, 128>>>(qkv, att);
        bgemm_ln<<<MB2, 256, ln_smem>>>(att, C_DIM, w_caow,
                                        ca_ob + (size_t)l*256, OT,
                                        ln_g + (size_t)(l*3 + 1)*C_DIM,
                                        ln_b + (size_t)(l*3 + 1)*C_DIM,
                                        LI, LIh, C_DIM);

        // ---- FFN ----
        bgemm_t<1><<<dim3(FF_DIM/128, MB), 256>>>(LIh, C_DIM, w_ff1, C_DIM,
                                                  b1f + (size_t)l*FF_DIM, h, FF_DIM, C_DIM, 1);
        bgemm_ln<<<MB2, 256, ln_smem>>>(h, FF_DIM, w_ff2,
                                        b2f + (size_t)l*256, LI,
                                        ln_g + (size_t)(l*3 + 2)*C_DIM,
                                        ln_b + (size_t)(l*3 + 2)*C_DIM,
                                        OT, OTh, FF_DIM);

        float* t0 = LI; LI = OT; OT = t0;
        bf16*  t1 = LIh; LIh = OTh; OTh = t1;
    }

    final_out_kernel<<<dim3(128, 8, 4), dim3(32, 8)>>>(LI, (float*)d_out);
}

// round 13
// speedup vs baseline: 1.0231x; 1.0231x over previous
#include <cuda_runtime.h>
#include <cuda_bf16.h>
#include <math.h>
#include <stdint.h>

// Problem constants
#define B_SZ     4
#define C_DIM    256
#define T_LEN    4096
#define FF_DIM   1024
#define NLAYERS  2
#define CHUNK    128
#define S_LEN    384          // 3*CHUNK
#define NW       32           // T/CHUNK
#define NSEQ     128          // B*NW
#define M_TOTAL  49152        // NSEQ*S_LEN
#define NHEADS   8
#define DH       32
#define EPS      1e-5f

typedef __nv_bfloat16  bf16;
typedef __nv_bfloat162 bf162;

// ---------------------------------------------------------------------------
// Device scratch. Residual stream fp32 with bf16 mirrors; big intermediates bf16.
// ---------------------------------------------------------------------------
__device__ float g_bufA [M_TOTAL * C_DIM];
__device__ float g_bufB [M_TOTAL * C_DIM];
__device__ float g_proj [M_TOTAL * C_DIM];
__device__ bf16  g_bufAh[M_TOTAL * C_DIM];
__device__ bf16  g_bufBh[M_TOTAL * C_DIM];
__device__ bf16  g_qkv  [M_TOTAL * 768];
__device__ bf16  g_att  [M_TOTAL * C_DIM];
__device__ bf16  g_h    [M_TOTAL * FF_DIM];
__device__ bf16  g_wbf  [2097152];           // all weights, bf16

// bf16 weight buffer offsets (elems)
#define OFF_SAW   0         // 2 x 196608
#define OFF_SAOW  393216    // 2 x 65536
#define OFF_CAW   524288    // 2 x 196608
#define OFF_CAOW  917504    // 2 x 65536
#define OFF_W1    1048576   // 2 x 262144
#define OFF_W2    1572864   // 2 x 262144

// ---------------------------------------------------------------------------
// helpers
// ---------------------------------------------------------------------------
__device__ __forceinline__ uint32_t packbf(float x, float y)
{
    bf162 h = __floats2bfloat162_rn(x, y);
    return *(uint32_t*)&h;
}

__device__ __forceinline__ void mma_bf16(float* c, const uint32_t* a, const uint32_t* b)
{
    asm volatile("mma.sync.aligned.m16n8k16.row.col.f32.bf16.bf16.f32 "
                 "{%0,%1,%2,%3}, {%4,%5,%6,%7}, {%8,%9}, {%0,%1,%2,%3};"
                 : "+f"(c[0]), "+f"(c[1]), "+f"(c[2]), "+f"(c[3])
                 : "r"(a[0]), "r"(a[1]), "r"(a[2]), "r"(a[3]),
                   "r"(b[0]), "r"(b[1]));
}

__device__ __forceinline__ void ldsm_x4b(uint32_t* d, const bf16* p)
{
    uint32_t a = (uint32_t)__cvta_generic_to_shared(p);
    asm volatile("ldmatrix.sync.aligned.m8n8.x4.shared.b16 {%0,%1,%2,%3}, [%4];"
                 : "=r"(d[0]), "=r"(d[1]), "=r"(d[2]), "=r"(d[3]) : "r"(a));
}

// ---------------------------------------------------------------------------
// Weight fp32 -> bf16 conversion
// ---------------------------------------------------------------------------
__global__ void convert_w_kernel(const float* __restrict__ src, bf16* __restrict__ dst, int n4)
{
    int i = blockIdx.x * blockDim.x + threadIdx.x;
    if (i < n4) {
        float4 v = ((const float4*)src)[i];
        bf162 a = __floats2bfloat162_rn(v.x, v.y);
        bf162 b = __floats2bfloat162_rn(v.z, v.w);
        ((bf162*)dst)[2 * i]     = a;
        ((bf162*)dst)[2 * i + 1] = b;
    }
}

// Dual-source variant so two weight tensors convert in ONE launch.
// Grid.x must cover max(n40, n41); the i<n4 guard handles the smaller one.
__global__ void convert_w2_kernel(const float* __restrict__ s0, bf16* __restrict__ d0, int n40,
                                  const float* __restrict__ s1, bf16* __restrict__ d1, int n41)
{
    int i = blockIdx.x * blockDim.x + threadIdx.x;
    const float* src = blockIdx.y ? s1 : s0;
    bf16*        dst = blockIdx.y ? d1 : d0;
    int          n4  = blockIdx.y ? n41 : n40;
    if (i < n4) {
        float4 v = ((const float4*)src)[i];
        bf162 a = __floats2bfloat162_rn(v.x, v.y);
        bf162 b = __floats2bfloat162_rn(v.z, v.w);
        ((bf162*)dst)[2 * i]     = a;
        ((bf162*)dst)[2 * i + 1] = b;
    }
}

// ---------------------------------------------------------------------------
// build_x: window gather + PE; writes fp32 + bf16 mirror
// ---------------------------------------------------------------------------
__global__ void build_x_kernel(const float* __restrict__ mem, float* __restrict__ x,
                               bf16* __restrict__ xh)
{
    __shared__ float tile[32][33];
    int p0 = blockIdx.x * 32, c0 = blockIdx.y * 32, seq = blockIdx.z;
    int b = seq >> 5, w = seq & 31;
    int tx = threadIdx.x, ty = threadIdx.y;
    int t_off = w * CHUNK + p0 - CHUNK;
    #pragma unroll
    for (int i = ty; i < 32; i += 8) {
        int tpos = t_off + tx;
        float v = 0.f;
        if (tpos >= 0 && tpos < T_LEN)
            v = mem[((size_t)b * C_DIM + c0 + i) * T_LEN + tpos];
        tile[i][tx] = v;
    }
    __syncthreads();
    #pragma unroll
    for (int i = ty; i < 32; i += 8) {
        int p = p0 + i;
        int c = c0 + tx;
        int j = c >> 1;
        float dv  = __expf((float)(2 * j) * (-9.210340371976184f / (float)C_DIM));
        float ang = (float)p * dv;
        float pe  = (c & 1) ? cosf(ang) : sinf(ang);
        float val = tile[tx][i] + pe;
        size_t idx = ((size_t)seq * S_LEN + p) * C_DIM + c;
        x[idx]  = val;
        xh[idx] = __float2bfloat16_rn(val);
    }
}

// ---------------------------------------------------------------------------
// bf16 GEMM (m16n8k16).  C[m,n] = sum_k A[m,k]*W[n,k] + bias[n] (+ReLU)
// Block 128x128, BK=32, 8 warps 2x4, warp 64x32. smem stride 40 bf16.
// ---------------------------------------------------------------------------
#define GSTR 40
template<int CBF16>
__global__ __launch_bounds__(256, 2)
void bgemm_t(const bf16* __restrict__ A, int lda,
             const bf16* __restrict__ W, int ldw,
             const float* __restrict__ bias,
             void* __restrict__ Cv, int ldc,
             int K, int doRelu)
{
    __shared__ __align__(16) bf16 As[2][128 * GSTR];
    __shared__ __align__(16) bf16 Bs[2][128 * GSTR];

    int tid  = threadIdx.x;
    int lane = tid & 31;
    int warp = tid >> 5;
    int wm = warp & 1;
    int wn = warp >> 1;
    int bm = blockIdx.y, bn = blockIdx.x;
    int r  = lane >> 2;
    int cc = lane & 3;

    int srow = tid & 127;
    int soff = (tid >> 7) * 16;
    const bf16* Ap = A + (size_t)(bm * 128 + srow) * lda + soff;
    const bf16* Wp = W + (size_t)(bn * 128 + srow) * ldw + soff;

    int a_row = wm * 64 + (lane & 15);
    int a_col = ((lane >> 4) & 1) * 8;
    int b_row = wn * 32 + (lane >> 4) * 8 + (lane & 7);
    int b_col = ((lane >> 3) & 1) * 8;

    float acc[4][4][4];
    #pragma unroll
    for (int i = 0; i < 4; i++)
        #pragma unroll
        for (int j = 0; j < 4; j++)
            #pragma unroll
            for (int q = 0; q < 4; q++) acc[i][j][q] = 0.f;

    {
        uint4 a0 = *(const uint4*)(Ap);
        uint4 a1 = *(const uint4*)(Ap + 8);
        uint4 b0 = *(const uint4*)(Wp);
        uint4 b1 = *(const uint4*)(Wp + 8);
        *(uint4*)&As[0][srow * GSTR + soff]     = a0;
        *(uint4*)&As[0][srow * GSTR + soff + 8] = a1;
        *(uint4*)&Bs[0][srow * GSTR + soff]     = b0;
        *(uint4*)&Bs[0][srow * GSTR + soff + 8] = b1;
    }
    __syncthreads();

    int niter = K >> 5;
    uint4 pa0, pa1, pb0, pb1;
    for (int it = 0; it < niter; it++) {
        int cur = it & 1;
        if (it + 1 < niter) {
            pa0 = *(const uint4*)(Ap + (it + 1) * 32);
            pa1 = *(const uint4*)(Ap + (it + 1) * 32 + 8);
            pb0 = *(const uint4*)(Wp + (it + 1) * 32);
            pb1 = *(const uint4*)(Wp + (it + 1) * 32 + 8);
        }

        const bf16* Ac = As[cur];
        const bf16* Bc = Bs[cur];
        #pragma unroll
        for (int kb = 0; kb < 2; kb++) {
            uint32_t af[4][4];
            uint32_t bfr[4][2];
            #pragma unroll
            for (int mt = 0; mt < 4; mt++)
                ldsm_x4b(af[mt], Ac + (a_row + mt * 16) * GSTR + kb * 16 + a_col);
            #pragma unroll
            for (int np = 0; np < 2; np++) {
                uint32_t t4[4];
                ldsm_x4b(t4, Bc + (b_row + np * 16) * GSTR + kb * 16 + b_col);
                bfr[2 * np][0]     = t4[0];
                bfr[2 * np][1]     = t4[1];
                bfr[2 * np + 1][0] = t4[2];
                bfr[2 * np + 1][1] = t4[3];
            }
            #pragma unroll
            for (int mt = 0; mt < 4; mt++)
                #pragma unroll
                for (int nt = 0; nt < 4; nt++)
                    mma_bf16(acc[mt][nt], af[mt], bfr[nt]);
        }

        if (it + 1 < niter) {
            int nxt = cur ^ 1;
            *(uint4*)&As[nxt][srow * GSTR + soff]     = pa0;
            *(uint4*)&As[nxt][srow * GSTR + soff + 8] = pa1;
            *(uint4*)&Bs[nxt][srow * GSTR + soff]     = pb0;
            *(uint4*)&Bs[nxt][srow * GSTR + soff + 8] = pb1;
        }
        __syncthreads();
    }

    int c2 = cc * 2;
    #pragma unroll
    for (int mt = 0; mt < 4; mt++) {
        int row0 = bm * 128 + wm * 64 + mt * 16 + r;
        #pragma unroll
        for (int nt = 0; nt < 4; nt++) {
            int col = bn * 128 + wn * 32 + nt * 8 + c2;
            float bx = bias[col], by = bias[col + 1];
            float2 v0, v1;
            v0.x = acc[mt][nt][0] + bx; v0.y = acc[mt][nt][1] + by;
            v1.x = acc[mt][nt][2] + bx; v1.y = acc[mt][nt][3] + by;
            if (doRelu) {
                v0.x = fmaxf(v0.x, 0.f); v0.y = fmaxf(v0.y, 0.f);
                v1.x = fmaxf(v1.x, 0.f); v1.y = fmaxf(v1.y, 0.f);
            }
            if (CBF16) {
                bf16* Cp = (bf16*)Cv;
                *(bf162*)(Cp + (size_t)row0 * ldc + col)       = __float22bfloat162_rn(v0);
                *(bf162*)(Cp + (size_t)(row0 + 8) * ldc + col) = __float22bfloat162_rn(v1);
            } else {
                float* Cp = (float*)Cv;
                *(float2*)(Cp + (size_t)row0 * ldc + col)       = v0;
                *(float2*)(Cp + (size_t)(row0 + 8) * ldc + col) = v1;
            }
        }
    }
}

// ---------------------------------------------------------------------------
// bf16 MMA flash attention v2: ONE block per (seq, head). Grid (NSEQ, NHEADS),
// 128 threads. ALL 384 keys of K and V staged ONCE into smem (55.8 KB dyn),
// a single __syncthreads, then 3 q-chunks x 6 KV tiles computed from
// resident smem. K/V gmem traffic 1/3 of the per-q-block scheme.
// Ks[key=384][dim, str 40], Vs[dim=32][key, str 392].
// ---------------------------------------------------------------------------
#define KSB  40
#define VST  392
#define ATT_SMEM_BYTES ((S_LEN * KSB + DH * VST) * (int)sizeof(bf16))   // 55808

__global__ __launch_bounds__(128)
void attn_bf16_kernel(const bf16* __restrict__ qkv, bf16* __restrict__ att)
{
    extern __shared__ __align__(16) bf16 smb[];
    bf16* Ks = smb;                    // 384 * 40
    bf16* Vs = smb + S_LEN * KSB;      // 32 * 392

    int tid  = threadIdx.x;
    int lane = tid & 31, warp = tid >> 5;
    int r = lane >> 2, cc = lane & 3;
    int seq = blockIdx.x, h = blockIdx.y;
    const bf16* base = qkv + (size_t)seq * S_LEN * 768;

    int brow = (lane & 7) + ((lane >> 4) & 1) * 8;
    int bcol = ((lane >> 3) & 1) * 8;

    // ---- stage ALL K (384 keys x 32 dims) ----
    #pragma unroll
    for (int i = 0; i < 6; i++) {
        int lin = i * 128 + tid;        // 0..767
        int key = lin >> 1;
        int ch  = (lin & 1) * 16;
        const bf16* src = base + (size_t)key * 768 + 256 + h * DH + ch;
        uint4 k0 = *(const uint4*)src;
        uint4 k1 = *(const uint4*)(src + 8);
        *(uint4*)&Ks[key * KSB + ch]     = k0;
        *(uint4*)&Ks[key * KSB + ch + 8] = k1;
    }
    // ---- stage ALL V transposed [dim][key] ----
    #pragma unroll
    for (int i = 0; i < 6; i++) {
        int kp  = tid & 31;             // key pair within 64-key tile
        int oct = tid >> 5;             // dim octet
        int keyb = i * 64 + 2 * kp;
        const bf16* v0 = base + (size_t)keyb * 768 + 512 + h * DH + oct * 8;
        uint4 ra = *(const uint4*)v0;
        uint4 rb = *(const uint4*)(v0 + 768);
        const bf16* va = (const bf16*)&ra;
        const bf16* vb = (const bf16*)&rb;
        #pragma unroll
        for (int d = 0; d < 8; d++) {
            bf162 pr;
            pr.x = va[d]; pr.y = vb[d];
            *(bf162*)&Vs[(oct * 8 + d) * VST + keyb] = pr;
        }
    }
    __syncthreads();

    // ---- 3 q-chunks of 128 (32 per warp) ----
    for (int qc = 0; qc < 3; qc++) {
        int qbase = qc * 128 + warp * 32;

        // Q fragments (m16k16 x 2 ksteps), pre-scaled, bf16
        uint32_t qa[2][2][4];
        #pragma unroll
        for (int mt = 0; mt < 2; mt++) {
            const bf16* q0 = base + (size_t)(qbase + mt * 16 + r) * 768 + h * DH;
            const bf16* q1 = q0 + 8 * 768;
            const float sc = 0.17677669529663687f;   // 1/sqrt(32)
            #pragma unroll
            for (int kb = 0; kb < 2; kb++) {
                bf162 p00 = *(const bf162*)(q0 + kb * 16 + 2 * cc);
                bf162 p01 = *(const bf162*)(q0 + kb * 16 + 2 * cc + 8);
                bf162 p10 = *(const bf162*)(q1 + kb * 16 + 2 * cc);
                bf162 p11 = *(const bf162*)(q1 + kb * 16 + 2 * cc + 8);
                float2 f;
                f = __bfloat1622float2(p00); qa[mt][kb][0] = packbf(f.x * sc, f.y * sc);
                f = __bfloat1622float2(p10); qa[mt][kb][1] = packbf(f.x * sc, f.y * sc);
                f = __bfloat1622float2(p01); qa[mt][kb][2] = packbf(f.x * sc, f.y * sc);
                f = __bfloat1622float2(p11); qa[mt][kb][3] = packbf(f.x * sc, f.y * sc);
            }
        }

        float lrun[2][2], oacc[2][4][4];
        #pragma unroll
        for (int mt = 0; mt < 2; mt++) {
            lrun[mt][0] = 0.f; lrun[mt][1] = 0.f;
            #pragma unroll
            for (int nt = 0; nt < 4; nt++)
                #pragma unroll
                for (int q = 0; q < 4; q++) oacc[mt][nt][q] = 0.f;
        }

        for (int kt = 0; kt < 6; kt++) {
            int kt64 = kt * 64;

            // QK^T for this 64-key tile
            float sacc[2][8][4];
            #pragma unroll
            for (int mt = 0; mt < 2; mt++)
                #pragma unroll
                for (int nt = 0; nt < 8; nt++)
                    #pragma unroll
                    for (int q = 0; q < 4; q++) sacc[mt][nt][q] = 0.f;

            #pragma unroll
            for (int kb = 0; kb < 2; kb++) {
                #pragma unroll
                for (int kq = 0; kq < 4; kq++) {
                    uint32_t t4[4];
                    ldsm_x4b(t4, Ks + (kt64 + kq * 16 + brow) * KSB + kb * 16 + bcol);
                    #pragma unroll
                    for (int mt = 0; mt < 2; mt++) {
                        mma_bf16(sacc[mt][2 * kq],     qa[mt][kb], t4);
                        mma_bf16(sacc[mt][2 * kq + 1], qa[mt][kb], t4 + 2);
                    }
                }
            }

            // softmax (no max shift; scores bounded) + PV, P register-resident
            #pragma unroll
            for (int kg = 0; kg < 4; kg++) {
                uint32_t bv[4][2];
                #pragma unroll
                for (int np = 0; np < 2; np++) {
                    uint32_t t4[4];
                    ldsm_x4b(t4, Vs + (np * 16 + brow) * VST + kt64 + kg * 16 + bcol);
                    bv[2 * np][0]     = t4[0];
                    bv[2 * np][1]     = t4[1];
                    bv[2 * np + 1][0] = t4[2];
                    bv[2 * np + 1][1] = t4[3];
                }
                #pragma unroll
                for (int mt = 0; mt < 2; mt++) {
                    float e0 = __expf(sacc[mt][2 * kg][0]);
                    float e1 = __expf(sacc[mt][2 * kg][1]);
                    float e2 = __expf(sacc[mt][2 * kg][2]);
                    float e3 = __expf(sacc[mt][2 * kg][3]);
                    float e4 = __expf(sacc[mt][2 * kg + 1][0]);
                    float e5 = __expf(sacc[mt][2 * kg + 1][1]);
                    float e6 = __expf(sacc[mt][2 * kg + 1][2]);
                    float e7 = __expf(sacc[mt][2 * kg + 1][3]);
                    lrun[mt][0] += e0 + e1 + e4 + e5;
                    lrun[mt][1] += e2 + e3 + e6 + e7;
                    uint32_t af[4];
                    af[0] = packbf(e0, e1);
                    af[1] = packbf(e2, e3);
                    af[2] = packbf(e4, e5);
                    af[3] = packbf(e6, e7);
                    #pragma unroll
                    for (int nt = 0; nt < 4; nt++)
                        mma_bf16(oacc[mt][nt], af, bv[nt]);
                }
            }
        }

        // finalize this q-chunk
        #pragma unroll
        for (int mt = 0; mt < 2; mt++) {
            float l0 = lrun[mt][0];
            l0 += __shfl_xor_sync(0xFFFFFFFFu, l0, 1);
            l0 += __shfl_xor_sync(0xFFFFFFFFu, l0, 2);
            float l1 = lrun[mt][1];
            l1 += __shfl_xor_sync(0xFFFFFFFFu, l1, 1);
            l1 += __shfl_xor_sync(0xFFFFFFFFu, l1, 2);
            float inv0 = 1.f / l0, inv1 = 1.f / l1;
            size_t grow = (size_t)seq * S_LEN + qbase + mt * 16 + r;
            #pragma unroll
            for (int nt = 0; nt < 4; nt++) {
                int col = h * DH + nt * 8 + 2 * cc;
                float2 v0, v1;
                v0.x = oacc[mt][nt][0] * inv0; v0.y = oacc[mt][nt][1] * inv0;
                v1.x = oacc[mt][nt][2] * inv1; v1.y = oacc[mt][nt][3] * inv1;
                *(bf162*)(att + grow * C_DIM + col)       = __float22bfloat162_rn(v0);
                *(bf162*)(att + (grow + 8) * C_DIM + col) = __float22bfloat162_rn(v1);
            }
        }
    }
}

// ---------------------------------------------------------------------------
// Residual add + LayerNorm; writes fp32 + bf16 mirror.
// ---------------------------------------------------------------------------
__global__ void add_ln_kernel(const float* __restrict__ x, const float* __restrict__ hres,
                              const float* __restrict__ g, const float* __restrict__ b,
                              float* __restrict__ out, bf16* __restrict__ outh)
{
    int tx = threadIdx.x, ty = threadIdx.y;
    int row = blockIdx.x * 4 + ty;
    size_t base = (size_t)row * C_DIM + tx * 4;
    float4 xv = *(const float4*)(x + base);
    float4 hv = *(const float4*)(hres + base);
    float4 v;
    v.x = xv.x + hv.x; v.y = xv.y + hv.y; v.z = xv.z + hv.z; v.w = xv.w + hv.w;
    float s  = v.x + v.y + v.z + v.w;
    float s2 = v.x * v.x + v.y * v.y + v.z * v.z + v.w * v.w;
    #pragma unroll
    for (int off = 16; off; off >>= 1) {
        s  += __shfl_xor_sync(0xFFFFFFFFu, s,  off);
        s2 += __shfl_xor_sync(0xFFFFFFFFu, s2, off);
    }
    __shared__ float red[4][2][2];
    int wh = tx >> 5;
    if ((tx & 31) == 0) { red[ty][wh][0] = s; red[ty][wh][1] = s2; }
    __syncthreads();
    float ts  = red[ty][0][0] + red[ty][1][0];
    float ts2 = red[ty][0][1] + red[ty][1][1];
    float mean = ts * (1.f / C_DIM);
    float var  = ts2 * (1.f / C_DIM) - mean * mean;
    float rstd = rsqrtf(var + EPS);
    float4 gv = *(const float4*)(g + tx * 4);
    float4 bv = *(const float4*)(b + tx * 4);
    float4 o;
    o.x = (v.x - mean) * rstd * gv.x + bv.x;
    o.y = (v.y - mean) * rstd * gv.y + bv.y;
    o.z = (v.z - mean) * rstd * gv.z + bv.z;
    o.w = (v.w - mean) * rstd * gv.w + bv.w;
    *(float4*)(out + base) = o;
    bf162 h0 = __floats2bfloat162_rn(o.x, o.y);
    bf162 h1 = __floats2bfloat162_rn(o.z, o.w);
    uint2 pk;
    pk.x = *(uint32_t*)&h0;
    pk.y = *(uint32_t*)&h1;
    *(uint2*)(outh + base) = pk;
}

// ---------------------------------------------------------------------------
// Final gather
// ---------------------------------------------------------------------------
__global__ void final_out_kernel(const float* __restrict__ x, float* __restrict__ out)
{
    __shared__ float tile[32][33];
    int t0 = blockIdx.x * 32, c0 = blockIdx.y * 32, b = blockIdx.z;
    int tx = threadIdx.x, ty = threadIdx.y;
    #pragma unroll
    for (int i = ty; i < 32; i += 8) {
        int t = t0 + i;
        size_t row = (size_t)(b * NW + (t >> 7)) * S_LEN + CHUNK + (t & 127);
        tile[i][tx] = x[row * C_DIM + c0 + tx];
    }
    __syncthreads();
    #pragma unroll
    for (int i = ty; i < 32; i += 8)
        out[((size_t)b * C_DIM + c0 + i) * T_LEN + t0 + tx] = tile[tx][i];
}

// ---------------------------------------------------------------------------
// Host orchestration.  Attention kernel sits at global launch index 5 so
// ncu (-s 5 -c 1) profiles it.
// ---------------------------------------------------------------------------
extern "C" void kernel_launch(void* const* d_in, const int* in_sizes, int n_in,
                              void* d_out, int out_size)
{
    (void)in_sizes; (void)n_in; (void)out_size;
    const float* mem   = (const float*)d_in[0];
    const float* sa_w  = (const float*)d_in[1];
    const float* sa_b  = (const float*)d_in[2];
    const float* sa_ow = (const float*)d_in[3];
    const float* sa_ob = (const float*)d_in[4];
    const float* ca_w  = (const float*)d_in[5];
    const float* ca_b  = (const float*)d_in[6];
    const float* ca_ow = (const float*)d_in[7];
    const float* ca_ob = (const float*)d_in[8];
    const float* w1    = (const float*)d_in[9];
    const float* b1f   = (const float*)d_in[10];
    const float* w2    = (const float*)d_in[11];
    const float* b2f   = (const float*)d_in[12];
    const float* ln_g  = (const float*)d_in[13];
    const float* ln_b  = (const float*)d_in[14];

    float *bufA, *bufB, *proj;
    bf16 *bufAh, *bufBh, *qkv, *att, *h, *wbf;
    cudaGetSymbolAddress((void**)&bufA,  g_bufA);
    cudaGetSymbolAddress((void**)&bufB,  g_bufB);
    cudaGetSymbolAddress((void**)&proj,  g_proj);
    cudaGetSymbolAddress((void**)&bufAh, g_bufAh);
    cudaGetSymbolAddress((void**)&bufBh, g_bufBh);
    cudaGetSymbolAddress((void**)&qkv,   g_qkv);
    cudaGetSymbolAddress((void**)&att,   g_att);
    cudaGetSymbolAddress((void**)&h,     g_h);
    cudaGetSymbolAddress((void**)&wbf,   g_wbf);

    cudaFuncSetAttribute(attn_bf16_kernel, cudaFuncAttributeMaxDynamicSharedMemorySize,
                         ATT_SMEM_BYTES);

    const int MB = M_TOTAL / 128;   // 384
    dim3 attn_grid(NSEQ, NHEADS);

    float* LI = bufA;   bf16* LIh = bufAh;
    float* OT = bufB;   bf16* OTh = bufBh;

    // --- launches 0..2: weight converts needed before launch 4 ---
    convert_w_kernel<<< 384, 256>>>(sa_w,  wbf + OFF_SAW,   98304);   // 0
    convert_w_kernel<<< 128, 256>>>(sa_ow, wbf + OFF_SAOW,  32768);   // 1
    convert_w_kernel<<< 384, 256>>>(ca_w,  wbf + OFF_CAW,   98304);   // 2
    // --- launch 3: build x ---
    build_x_kernel<<<dim3(12, 8, NSEQ), dim3(32, 8)>>>(mem, bufA, bufAh);   // 3

    for (int l = 0; l < NLAYERS; l++) {
        const bf16* w_qkv  = wbf + OFF_SAW  + (size_t)l * 196608;
        const bf16* w_saow = wbf + OFF_SAOW + (size_t)l * 65536;
        const bf16* w_caw  = wbf + OFF_CAW  + (size_t)l * 196608;
        const bf16* w_caow = wbf + OFF_CAOW + (size_t)l * 65536;
        const bf16* w_ff1  = wbf + OFF_W1   + (size_t)l * 262144;
        const bf16* w_ff2  = wbf + OFF_W2   + (size_t)l * 262144;

        // ---- self attention ----  (layer 0: launches 4 and 5)
        bgemm_t<1><<<dim3(768/128, MB), 256>>>(LIh, C_DIM, w_qkv, C_DIM,
                                               sa_b + (size_t)l*768, qkv, 768, C_DIM, 0);
        attn_bf16_kernel<<<attn_grid, 128, ATT_SMEM_BYTES>>>(qkv, att);   // launch 5 (l=0)
        bgemm_t<0><<<dim3(256/128, MB), 256>>>(att, C_DIM, w_saow, C_DIM,
                                               sa_ob + (size_t)l*256, proj, 256, C_DIM, 0);
        add_ln_kernel<<<M_TOTAL/4, dim3(64, 4)>>>(LI, proj,
                                                  ln_g + (size_t)(l*3 + 0)*C_DIM,
                                                  ln_b + (size_t)(l*3 + 0)*C_DIM, OT, OTh);

        if (l == 0) {
            // remaining weight converts; grid.x covers the LARGER tensor (w1: 131072/256 = 512)
            convert_w2_kernel<<<dim3(512, 2), 256>>>(ca_ow, wbf + OFF_CAOW, 32768,
                                                     w1,    wbf + OFF_W1,  131072);
            convert_w_kernel<<< 512, 256>>>(w2, wbf + OFF_W2, 131072);
        }

        // ---- cross attention (Q from OT=x1, K/V from LI=layer input) ----
        bgemm_t<1><<<dim3(256/128, MB), 256>>>(OTh, C_DIM, w_caw, C_DIM,
                                               ca_b + (size_t)l*768, qkv, 768, C_DIM, 0);
        bgemm_t<1><<<dim3(512/128, MB), 256>>>(LIh, C_DIM, w_caw + 256*256, C_DIM,
                                               ca_b + (size_t)l*768 + 256, qkv + 256, 768, C_DIM, 0);
        attn_bf16_kernel<<<attn_grid, 128, ATT_SMEM_BYTES>>>(qkv, att);
        bgemm_t<0><<<dim3(256/128, MB), 256>>>(att, C_DIM, w_caow, C_DIM,
                                               ca_ob + (size_t)l*256, proj, 256, C_DIM, 0);
        add_ln_kernel<<<M_TOTAL/4, dim3(64, 4)>>>(OT, proj,
                                                  ln_g + (size_t)(l*3 + 1)*C_DIM,
                                                  ln_b + (size_t)(l*3 + 1)*C_DIM, LI, LIh);

        // ---- FFN ----
        bgemm_t<1><<<dim3(FF_DIM/128, MB), 256>>>(LIh, C_DIM, w_ff1, C_DIM,
                                                  b1f + (size_t)l*FF_DIM, h, FF_DIM, C_DIM, 1);
        bgemm_t<0><<<dim3(256/128, MB), 256>>>(h, FF_DIM, w_ff2, FF_DIM,
                                               b2f + (size_t)l*256, proj, 256, FF_DIM, 0);
        add_ln_kernel<<<M_TOTAL/4, dim3(64, 4)>>>(LI, proj,
                                                  ln_g + (size_t)(l*3 + 2)*C_DIM,
                                                  ln_b + (size_t)(l*3 + 2)*C_DIM, OT, OTh);

        float* t0 = LI; LI = OT; OT = t0;
        bf16*  t1 = LIh; LIh = OTh; OTh = t1;
    }

    final_out_kernel<<<dim3(128, 8, 4), dim3(32, 8)>>>(LI, (float*)d_out);
}

// round 14
// speedup vs baseline: 1.0393x; 1.0159x over previous
#include <cuda_runtime.h>
#include <cuda_bf16.h>
#include <math.h>
#include <stdint.h>

// Problem constants
#define B_SZ     4
#define C_DIM    256
#define T_LEN    4096
#define FF_DIM   1024
#define NLAYERS  2
#define CHUNK    128
#define S_LEN    384          // 3*CHUNK
#define NW       32           // T/CHUNK
#define NSEQ     128          // B*NW
#define M_TOTAL  49152        // NSEQ*S_LEN
#define NHEADS   8
#define DH       32
#define EPS      1e-5f

typedef __nv_bfloat16  bf16;
typedef __nv_bfloat162 bf162;

// ---------------------------------------------------------------------------
// Device scratch. Residual stream fp32 with bf16 mirrors; big intermediates bf16.
// ---------------------------------------------------------------------------
__device__ float g_bufA [M_TOTAL * C_DIM];
__device__ float g_bufB [M_TOTAL * C_DIM];
__device__ float g_proj [M_TOTAL * C_DIM];
__device__ bf16  g_bufAh[M_TOTAL * C_DIM];
__device__ bf16  g_bufBh[M_TOTAL * C_DIM];
__device__ bf16  g_qkv  [M_TOTAL * 768];
__device__ bf16  g_att  [M_TOTAL * C_DIM];
__device__ bf16  g_h    [M_TOTAL * FF_DIM];
__device__ bf16  g_wbf  [2097152];           // all weights, bf16

// bf16 weight buffer offsets (elems)
#define OFF_SAW   0         // 2 x 196608
#define OFF_SAOW  393216    // 2 x 65536
#define OFF_CAW   524288    // 2 x 196608
#define OFF_CAOW  917504    // 2 x 65536
#define OFF_W1    1048576   // 2 x 262144
#define OFF_W2    1572864   // 2 x 262144

// ---------------------------------------------------------------------------
// helpers
// ---------------------------------------------------------------------------
__device__ __forceinline__ uint32_t packbf(float x, float y)
{
    bf162 h = __floats2bfloat162_rn(x, y);
    return *(uint32_t*)&h;
}

__device__ __forceinline__ void mma_bf16(float* c, const uint32_t* a, const uint32_t* b)
{
    asm volatile("mma.sync.aligned.m16n8k16.row.col.f32.bf16.bf16.f32 "
                 "{%0,%1,%2,%3}, {%4,%5,%6,%7}, {%8,%9}, {%0,%1,%2,%3};"
                 : "+f"(c[0]), "+f"(c[1]), "+f"(c[2]), "+f"(c[3])
                 : "r"(a[0]), "r"(a[1]), "r"(a[2]), "r"(a[3]),
                   "r"(b[0]), "r"(b[1]));
}

__device__ __forceinline__ void ldsm_x4b(uint32_t* d, const bf16* p)
{
    uint32_t a = (uint32_t)__cvta_generic_to_shared(p);
    asm volatile("ldmatrix.sync.aligned.m8n8.x4.shared.b16 {%0,%1,%2,%3}, [%4];"
                 : "=r"(d[0]), "=r"(d[1]), "=r"(d[2]), "=r"(d[3]) : "r"(a));
}

// ---------------------------------------------------------------------------
// Weight fp32 -> bf16 conversion
// ---------------------------------------------------------------------------
__global__ void convert_w_kernel(const float* __restrict__ src, bf16* __restrict__ dst, int n4)
{
    int i = blockIdx.x * blockDim.x + threadIdx.x;
    if (i < n4) {
        float4 v = ((const float4*)src)[i];
        bf162 a = __floats2bfloat162_rn(v.x, v.y);
        bf162 b = __floats2bfloat162_rn(v.z, v.w);
        ((bf162*)dst)[2 * i]     = a;
        ((bf162*)dst)[2 * i + 1] = b;
    }
}

// Dual-source variant: two weight tensors in one launch.
// grid.x must cover max(n40, n41); the i<n4 guard handles the smaller one.
__global__ void convert_w2_kernel(const float* __restrict__ s0, bf16* __restrict__ d0, int n40,
                                  const float* __restrict__ s1, bf16* __restrict__ d1, int n41)
{
    int i = blockIdx.x * blockDim.x + threadIdx.x;
    const float* src = blockIdx.y ? s1 : s0;
    bf16*        dst = blockIdx.y ? d1 : d0;
    int          n4  = blockIdx.y ? n41 : n40;
    if (i < n4) {
        float4 v = ((const float4*)src)[i];
        bf162 a = __floats2bfloat162_rn(v.x, v.y);
        bf162 b = __floats2bfloat162_rn(v.z, v.w);
        ((bf162*)dst)[2 * i]     = a;
        ((bf162*)dst)[2 * i + 1] = b;
    }
}

// ---------------------------------------------------------------------------
// build_x: window gather + PE; writes fp32 + bf16 mirror
// ---------------------------------------------------------------------------
__global__ void build_x_kernel(const float* __restrict__ mem, float* __restrict__ x,
                               bf16* __restrict__ xh)
{
    __shared__ float tile[32][33];
    int p0 = blockIdx.x * 32, c0 = blockIdx.y * 32, seq = blockIdx.z;
    int b = seq >> 5, w = seq & 31;
    int tx = threadIdx.x, ty = threadIdx.y;
    int t_off = w * CHUNK + p0 - CHUNK;
    #pragma unroll
    for (int i = ty; i < 32; i += 8) {
        int tpos = t_off + tx;
        float v = 0.f;
        if (tpos >= 0 && tpos < T_LEN)
            v = mem[((size_t)b * C_DIM + c0 + i) * T_LEN + tpos];
        tile[i][tx] = v;
    }
    __syncthreads();
    #pragma unroll
    for (int i = ty; i < 32; i += 8) {
        int p = p0 + i;
        int c = c0 + tx;
        int j = c >> 1;
        float dv  = __expf((float)(2 * j) * (-9.210340371976184f / (float)C_DIM));
        float ang = (float)p * dv;
        float pe  = (c & 1) ? cosf(ang) : sinf(ang);
        float val = tile[tx][i] + pe;
        size_t idx = ((size_t)seq * S_LEN + p) * C_DIM + c;
        x[idx]  = val;
        xh[idx] = __float2bfloat16_rn(val);
    }
}

// ---------------------------------------------------------------------------
// bf16 GEMM (m16n8k16).  C[m,n] = sum_k A[m,k]*W[n,k] + bias[n] (+ReLU)
// Block 128x128, BK=32, 8 warps 2x4, warp 64x32. smem stride 40 bf16.
// ---------------------------------------------------------------------------
#define GSTR 40
template<int CBF16>
__global__ __launch_bounds__(256, 2)
void bgemm_t(const bf16* __restrict__ A, int lda,
             const bf16* __restrict__ W, int ldw,
             const float* __restrict__ bias,
             void* __restrict__ Cv, int ldc,
             int K, int doRelu)
{
    __shared__ __align__(16) bf16 As[2][128 * GSTR];
    __shared__ __align__(16) bf16 Bs[2][128 * GSTR];

    int tid  = threadIdx.x;
    int lane = tid & 31;
    int warp = tid >> 5;
    int wm = warp & 1;
    int wn = warp >> 1;
    int bm = blockIdx.y, bn = blockIdx.x;
    int r  = lane >> 2;
    int cc = lane & 3;

    int srow = tid & 127;
    int soff = (tid >> 7) * 16;
    const bf16* Ap = A + (size_t)(bm * 128 + srow) * lda + soff;
    const bf16* Wp = W + (size_t)(bn * 128 + srow) * ldw + soff;

    int a_row = wm * 64 + (lane & 15);
    int a_col = ((lane >> 4) & 1) * 8;
    int b_row = wn * 32 + (lane >> 4) * 8 + (lane & 7);
    int b_col = ((lane >> 3) & 1) * 8;

    float acc[4][4][4];
    #pragma unroll
    for (int i = 0; i < 4; i++)
        #pragma unroll
        for (int j = 0; j < 4; j++)
            #pragma unroll
            for (int q = 0; q < 4; q++) acc[i][j][q] = 0.f;

    {
        uint4 a0 = *(const uint4*)(Ap);
        uint4 a1 = *(const uint4*)(Ap + 8);
        uint4 b0 = *(const uint4*)(Wp);
        uint4 b1 = *(const uint4*)(Wp + 8);
        *(uint4*)&As[0][srow * GSTR + soff]     = a0;
        *(uint4*)&As[0][srow * GSTR + soff + 8] = a1;
        *(uint4*)&Bs[0][srow * GSTR + soff]     = b0;
        *(uint4*)&Bs[0][srow * GSTR + soff + 8] = b1;
    }
    __syncthreads();

    int niter = K >> 5;
    uint4 pa0, pa1, pb0, pb1;
    for (int it = 0; it < niter; it++) {
        int cur = it & 1;
        if (it + 1 < niter) {
            pa0 = *(const uint4*)(Ap + (it + 1) * 32);
            pa1 = *(const uint4*)(Ap + (it + 1) * 32 + 8);
            pb0 = *(const uint4*)(Wp + (it + 1) * 32);
            pb1 = *(const uint4*)(Wp + (it + 1) * 32 + 8);
        }

        const bf16* Ac = As[cur];
        const bf16* Bc = Bs[cur];
        #pragma unroll
        for (int kb = 0; kb < 2; kb++) {
            uint32_t af[4][4];
            uint32_t bfr[4][2];
            #pragma unroll
            for (int mt = 0; mt < 4; mt++)
                ldsm_x4b(af[mt], Ac + (a_row + mt * 16) * GSTR + kb * 16 + a_col);
            #pragma unroll
            for (int np = 0; np < 2; np++) {
                uint32_t t4[4];
                ldsm_x4b(t4, Bc + (b_row + np * 16) * GSTR + kb * 16 + b_col);
                bfr[2 * np][0]     = t4[0];
                bfr[2 * np][1]     = t4[1];
                bfr[2 * np + 1][0] = t4[2];
                bfr[2 * np + 1][1] = t4[3];
            }
            #pragma unroll
            for (int mt = 0; mt < 4; mt++)
                #pragma unroll
                for (int nt = 0; nt < 4; nt++)
                    mma_bf16(acc[mt][nt], af[mt], bfr[nt]);
        }

        if (it + 1 < niter) {
            int nxt = cur ^ 1;
            *(uint4*)&As[nxt][srow * GSTR + soff]     = pa0;
            *(uint4*)&As[nxt][srow * GSTR + soff + 8] = pa1;
            *(uint4*)&Bs[nxt][srow * GSTR + soff]     = pb0;
            *(uint4*)&Bs[nxt][srow * GSTR + soff + 8] = pb1;
        }
        __syncthreads();
    }

    int c2 = cc * 2;
    #pragma unroll
    for (int mt = 0; mt < 4; mt++) {
        int row0 = bm * 128 + wm * 64 + mt * 16 + r;
        #pragma unroll
        for (int nt = 0; nt < 4; nt++) {
            int col = bn * 128 + wn * 32 + nt * 8 + c2;
            float bx = bias[col], by = bias[col + 1];
            float2 v0, v1;
            v0.x = acc[mt][nt][0] + bx; v0.y = acc[mt][nt][1] + by;
            v1.x = acc[mt][nt][2] + bx; v1.y = acc[mt][nt][3] + by;
            if (doRelu) {
                v0.x = fmaxf(v0.x, 0.f); v0.y = fmaxf(v0.y, 0.f);
                v1.x = fmaxf(v1.x, 0.f); v1.y = fmaxf(v1.y, 0.f);
            }
            if (CBF16) {
                bf16* Cp = (bf16*)Cv;
                *(bf162*)(Cp + (size_t)row0 * ldc + col)       = __float22bfloat162_rn(v0);
                *(bf162*)(Cp + (size_t)(row0 + 8) * ldc + col) = __float22bfloat162_rn(v1);
            } else {
                float* Cp = (float*)Cv;
                *(float2*)(Cp + (size_t)row0 * ldc + col)       = v0;
                *(float2*)(Cp + (size_t)(row0 + 8) * ldc + col) = v1;
            }
        }
    }
}

// ---------------------------------------------------------------------------
// bf16 MMA flash attention v3: one block per (seq, head), all K/V staged once.
// S processed in 32-key tiles (sacc 32 regs instead of 64) and
// __launch_bounds__(128, 4) -> 4 blocks/SM (regfile fits: <=128 regs).
// Ks[key=384][dim, str 40], Vs[dim=32][key, str 392].
// ---------------------------------------------------------------------------
#define KSB  40
#define VST  392
#define ATT_SMEM_BYTES ((S_LEN * KSB + DH * VST) * (int)sizeof(bf16))   // 55808

__global__ __launch_bounds__(128, 4)
void attn_bf16_kernel(const bf16* __restrict__ qkv, bf16* __restrict__ att)
{
    extern __shared__ __align__(16) bf16 smb[];
    bf16* Ks = smb;                    // 384 * 40
    bf16* Vs = smb + S_LEN * KSB;      // 32 * 392

    int tid  = threadIdx.x;
    int lane = tid & 31, warp = tid >> 5;
    int r = lane >> 2, cc = lane & 3;
    int seq = blockIdx.x, h = blockIdx.y;
    const bf16* base = qkv + (size_t)seq * S_LEN * 768;

    int brow = (lane & 7) + ((lane >> 4) & 1) * 8;
    int bcol = ((lane >> 3) & 1) * 8;

    // ---- stage ALL K (384 keys x 32 dims) ----
    #pragma unroll
    for (int i = 0; i < 6; i++) {
        int lin = i * 128 + tid;        // 0..767
        int key = lin >> 1;
        int ch  = (lin & 1) * 16;
        const bf16* src = base + (size_t)key * 768 + 256 + h * DH + ch;
        uint4 k0 = *(const uint4*)src;
        uint4 k1 = *(const uint4*)(src + 8);
        *(uint4*)&Ks[key * KSB + ch]     = k0;
        *(uint4*)&Ks[key * KSB + ch + 8] = k1;
    }
    // ---- stage ALL V transposed [dim][key] ----
    #pragma unroll
    for (int i = 0; i < 6; i++) {
        int kp  = tid & 31;
        int oct = tid >> 5;
        int keyb = i * 64 + 2 * kp;
        const bf16* v0 = base + (size_t)keyb * 768 + 512 + h * DH + oct * 8;
        uint4 ra = *(const uint4*)v0;
        uint4 rb = *(const uint4*)(v0 + 768);
        const bf16* va = (const bf16*)&ra;
        const bf16* vb = (const bf16*)&rb;
        #pragma unroll
        for (int d = 0; d < 8; d++) {
            bf162 pr;
            pr.x = va[d]; pr.y = vb[d];
            *(bf162*)&Vs[(oct * 8 + d) * VST + keyb] = pr;
        }
    }
    __syncthreads();

    // ---- 3 q-chunks of 128 (32 per warp) ----
    for (int qc = 0; qc < 3; qc++) {
        int qbase = qc * 128 + warp * 32;

        // Q fragments (m16k16 x 2 ksteps), pre-scaled, bf16
        uint32_t qa[2][2][4];
        #pragma unroll
        for (int mt = 0; mt < 2; mt++) {
            const bf16* q0 = base + (size_t)(qbase + mt * 16 + r) * 768 + h * DH;
            const bf16* q1 = q0 + 8 * 768;
            const float sc = 0.17677669529663687f;   // 1/sqrt(32)
            #pragma unroll
            for (int kb = 0; kb < 2; kb++) {
                bf162 p00 = *(const bf162*)(q0 + kb * 16 + 2 * cc);
                bf162 p01 = *(const bf162*)(q0 + kb * 16 + 2 * cc + 8);
                bf162 p10 = *(const bf162*)(q1 + kb * 16 + 2 * cc);
                bf162 p11 = *(const bf162*)(q1 + kb * 16 + 2 * cc + 8);
                float2 f;
                f = __bfloat1622float2(p00); qa[mt][kb][0] = packbf(f.x * sc, f.y * sc);
                f = __bfloat1622float2(p10); qa[mt][kb][1] = packbf(f.x * sc, f.y * sc);
                f = __bfloat1622float2(p01); qa[mt][kb][2] = packbf(f.x * sc, f.y * sc);
                f = __bfloat1622float2(p11); qa[mt][kb][3] = packbf(f.x * sc, f.y * sc);
            }
        }

        float lrun[2][2], oacc[2][4][4];
        #pragma unroll
        for (int mt = 0; mt < 2; mt++) {
            lrun[mt][0] = 0.f; lrun[mt][1] = 0.f;
            #pragma unroll
            for (int nt = 0; nt < 4; nt++)
                #pragma unroll
                for (int q = 0; q < 4; q++) oacc[mt][nt][q] = 0.f;
        }

        // 12 tiles of 32 keys (smaller sacc live range -> fewer registers)
        for (int kt = 0; kt < 12; kt++) {
            int kt32 = kt * 32;

            float sacc[2][4][4];
            #pragma unroll
            for (int mt = 0; mt < 2; mt++)
                #pragma unroll
                for (int nt = 0; nt < 4; nt++)
                    #pragma unroll
                    for (int q = 0; q < 4; q++) sacc[mt][nt][q] = 0.f;

            #pragma unroll
            for (int kb = 0; kb < 2; kb++) {
                #pragma unroll
                for (int kq = 0; kq < 2; kq++) {
                    uint32_t t4[4];
                    ldsm_x4b(t4, Ks + (kt32 + kq * 16 + brow) * KSB + kb * 16 + bcol);
                    #pragma unroll
                    for (int mt = 0; mt < 2; mt++) {
                        mma_bf16(sacc[mt][2 * kq],     qa[mt][kb], t4);
                        mma_bf16(sacc[mt][2 * kq + 1], qa[mt][kb], t4 + 2);
                    }
                }
            }

            // softmax (no max shift; scores bounded) + PV, P register-resident
            #pragma unroll
            for (int kg = 0; kg < 2; kg++) {
                uint32_t bv[4][2];
                #pragma unroll
                for (int np = 0; np < 2; np++) {
                    uint32_t t4[4];
                    ldsm_x4b(t4, Vs + (np * 16 + brow) * VST + kt32 + kg * 16 + bcol);
                    bv[2 * np][0]     = t4[0];
                    bv[2 * np][1]     = t4[1];
                    bv[2 * np + 1][0] = t4[2];
                    bv[2 * np + 1][1] = t4[3];
                }
                #pragma unroll
                for (int mt = 0; mt < 2; mt++) {
                    float e0 = __expf(sacc[mt][2 * kg][0]);
                    float e1 = __expf(sacc[mt][2 * kg][1]);
                    float e2 = __expf(sacc[mt][2 * kg][2]);
                    float e3 = __expf(sacc[mt][2 * kg][3]);
                    float e4 = __expf(sacc[mt][2 * kg + 1][0]);
                    float e5 = __expf(sacc[mt][2 * kg + 1][1]);
                    float e6 = __expf(sacc[mt][2 * kg + 1][2]);
                    float e7 = __expf(sacc[mt][2 * kg + 1][3]);
                    lrun[mt][0] += e0 + e1 + e4 + e5;
                    lrun[mt][1] += e2 + e3 + e6 + e7;
                    uint32_t af[4];
                    af[0] = packbf(e0, e1);
                    af[1] = packbf(e2, e3);
                    af[2] = packbf(e4, e5);
                    af[3] = packbf(e6, e7);
                    #pragma unroll
                    for (int nt = 0; nt < 4; nt++)
                        mma_bf16(oacc[mt][nt], af, bv[nt]);
                }
            }
        }

        // finalize this q-chunk
        #pragma unroll
        for (int mt = 0; mt < 2; mt++) {
            float l0 = lrun[mt][0];
            l0 += __shfl_xor_sync(0xFFFFFFFFu, l0, 1);
            l0 += __shfl_xor_sync(0xFFFFFFFFu, l0, 2);
            float l1 = lrun[mt][1];
            l1 += __shfl_xor_sync(0xFFFFFFFFu, l1, 1);
            l1 += __shfl_xor_sync(0xFFFFFFFFu, l1, 2);
            float inv0 = 1.f / l0, inv1 = 1.f / l1;
            size_t grow = (size_t)seq * S_LEN + qbase + mt * 16 + r;
            #pragma unroll
            for (int nt = 0; nt < 4; nt++) {
                int col = h * DH + nt * 8 + 2 * cc;
                float2 v0, v1;
                v0.x = oacc[mt][nt][0] * inv0; v0.y = oacc[mt][nt][1] * inv0;
                v1.x = oacc[mt][nt][2] * inv1; v1.y = oacc[mt][nt][3] * inv1;
                *(bf162*)(att + grow * C_DIM + col)       = __float22bfloat162_rn(v0);
                *(bf162*)(att + (grow + 8) * C_DIM + col) = __float22bfloat162_rn(v1);
            }
        }
    }
}

// ---------------------------------------------------------------------------
// Residual add + LayerNorm; writes fp32 + bf16 mirror.
// ---------------------------------------------------------------------------
__global__ void add_ln_kernel(const float* __restrict__ x, const float* __restrict__ hres,
                              const float* __restrict__ g, const float* __restrict__ b,
                              float* __restrict__ out, bf16* __restrict__ outh)
{
    int tx = threadIdx.x, ty = threadIdx.y;
    int row = blockIdx.x * 4 + ty;
    size_t base = (size_t)row * C_DIM + tx * 4;
    float4 xv = *(const float4*)(x + base);
    float4 hv = *(const float4*)(hres + base);
    float4 v;
    v.x = xv.x + hv.x; v.y = xv.y + hv.y; v.z = xv.z + hv.z; v.w = xv.w + hv.w;
    float s  = v.x + v.y + v.z + v.w;
    float s2 = v.x * v.x + v.y * v.y + v.z * v.z + v.w * v.w;
    #pragma unroll
    for (int off = 16; off; off >>= 1) {
        s  += __shfl_xor_sync(0xFFFFFFFFu, s,  off);
        s2 += __shfl_xor_sync(0xFFFFFFFFu, s2, off);
    }
    __shared__ float red[4][2][2];
    int wh = tx >> 5;
    if ((tx & 31) == 0) { red[ty][wh][0] = s; red[ty][wh][1] = s2; }
    __syncthreads();
    float ts  = red[ty][0][0] + red[ty][1][0];
    float ts2 = red[ty][0][1] + red[ty][1][1];
    float mean = ts * (1.f / C_DIM);
    float var  = ts2 * (1.f / C_DIM) - mean * mean;
    float rstd = rsqrtf(var + EPS);
    float4 gv = *(const float4*)(g + tx * 4);
    float4 bv = *(const float4*)(b + tx * 4);
    float4 o;
    o.x = (v.x - mean) * rstd * gv.x + bv.x;
    o.y = (v.y - mean) * rstd * gv.y + bv.y;
    o.z = (v.z - mean) * rstd * gv.z + bv.z;
    o.w = (v.w - mean) * rstd * gv.w + bv.w;
    *(float4*)(out + base) = o;
    bf162 h0 = __floats2bfloat162_rn(o.x, o.y);
    bf162 h1 = __floats2bfloat162_rn(o.z, o.w);
    uint2 pk;
    pk.x = *(uint32_t*)&h0;
    pk.y = *(uint32_t*)&h1;
    *(uint2*)(outh + base) = pk;
}

// ---------------------------------------------------------------------------
// Final gather
// ---------------------------------------------------------------------------
__global__ void final_out_kernel(const float* __restrict__ x, float* __restrict__ out)
{
    __shared__ float tile[32][33];
    int t0 = blockIdx.x * 32, c0 = blockIdx.y * 32, b = blockIdx.z;
    int tx = threadIdx.x, ty = threadIdx.y;
    #pragma unroll
    for (int i = ty; i < 32; i += 8) {
        int t = t0 + i;
        size_t row = (size_t)(b * NW + (t >> 7)) * S_LEN + CHUNK + (t & 127);
        tile[i][tx] = x[row * C_DIM + c0 + tx];
    }
    __syncthreads();
    #pragma unroll
    for (int i = ty; i < 32; i += 8)
        out[((size_t)b * C_DIM + c0 + i) * T_LEN + t0 + tx] = tile[tx][i];
}

// ---------------------------------------------------------------------------
// Host orchestration.  Attention is MY launch #3; harness adds 2 launches
// before mine, so ncu (-s 5 -c 1) should capture it.
// ---------------------------------------------------------------------------
extern "C" void kernel_launch(void* const* d_in, const int* in_sizes, int n_in,
                              void* d_out, int out_size)
{
    (void)in_sizes; (void)n_in; (void)out_size;
    const float* mem   = (const float*)d_in[0];
    const float* sa_w  = (const float*)d_in[1];
    const float* sa_b  = (const float*)d_in[2];
    const float* sa_ow = (const float*)d_in[3];
    const float* sa_ob = (const float*)d_in[4];
    const float* ca_w  = (const float*)d_in[5];
    const float* ca_b  = (const float*)d_in[6];
    const float* ca_ow = (const float*)d_in[7];
    const float* ca_ob = (const float*)d_in[8];
    const float* w1    = (const float*)d_in[9];
    const float* b1f   = (const float*)d_in[10];
    const float* w2    = (const float*)d_in[11];
    const float* b2f   = (const float*)d_in[12];
    const float* ln_g  = (const float*)d_in[13];
    const float* ln_b  = (const float*)d_in[14];

    float *bufA, *bufB, *proj;
    bf16 *bufAh, *bufBh, *qkv, *att, *h, *wbf;
    cudaGetSymbolAddress((void**)&bufA,  g_bufA);
    cudaGetSymbolAddress((void**)&bufB,  g_bufB);
    cudaGetSymbolAddress((void**)&proj,  g_proj);
    cudaGetSymbolAddress((void**)&bufAh, g_bufAh);
    cudaGetSymbolAddress((void**)&bufBh, g_bufBh);
    cudaGetSymbolAddress((void**)&qkv,   g_qkv);
    cudaGetSymbolAddress((void**)&att,   g_att);
    cudaGetSymbolAddress((void**)&h,     g_h);
    cudaGetSymbolAddress((void**)&wbf,   g_wbf);

    cudaFuncSetAttribute(attn_bf16_kernel, cudaFuncAttributeMaxDynamicSharedMemorySize,
                         ATT_SMEM_BYTES);

    const int MB = M_TOTAL / 128;   // 384
    dim3 attn_grid(NSEQ, NHEADS);

    float* LI = bufA;   bf16* LIh = bufAh;
    float* OT = bufB;   bf16* OTh = bufBh;

    // my-launch 0: convert sa_w (needed by qkv GEMM)
    convert_w_kernel<<< 384, 256>>>(sa_w, wbf + OFF_SAW, 98304);
    // my-launch 1: build x
    build_x_kernel<<<dim3(12, 8, NSEQ), dim3(32, 8)>>>(mem, bufA, bufAh);

    for (int l = 0; l < NLAYERS; l++) {
        const bf16* w_qkv  = wbf + OFF_SAW  + (size_t)l * 196608;
        const bf16* w_saow = wbf + OFF_SAOW + (size_t)l * 65536;
        const bf16* w_caw  = wbf + OFF_CAW  + (size_t)l * 196608;
        const bf16* w_caow = wbf + OFF_CAOW + (size_t)l * 65536;
        const bf16* w_ff1  = wbf + OFF_W1   + (size_t)l * 262144;
        const bf16* w_ff2  = wbf + OFF_W2   + (size_t)l * 262144;

        // ---- self attention ---- (l=0: my launches 2 and 3)
        bgemm_t<1><<<dim3(768/128, MB), 256>>>(LIh, C_DIM, w_qkv, C_DIM,
                                               sa_b + (size_t)l*768, qkv, 768, C_DIM, 0);
        attn_bf16_kernel<<<attn_grid, 128, ATT_SMEM_BYTES>>>(qkv, att);

        if (l == 0) {
            // remaining converts, all before first use
            convert_w2_kernel<<<dim3(384, 2), 256>>>(sa_ow, wbf + OFF_SAOW, 32768,
                                                     ca_w,  wbf + OFF_CAW,  98304);
            convert_w2_kernel<<<dim3(512, 2), 256>>>(ca_ow, wbf + OFF_CAOW, 32768,
                                                     w1,    wbf + OFF_W1,  131072);
            convert_w_kernel<<< 512, 256>>>(w2, wbf + OFF_W2, 131072);
        }

        bgemm_t<0><<<dim3(256/128, MB), 256>>>(att, C_DIM, w_saow, C_DIM,
                                               sa_ob + (size_t)l*256, proj, 256, C_DIM, 0);
        add_ln_kernel<<<M_TOTAL/4, dim3(64, 4)>>>(LI, proj,
                                                  ln_g + (size_t)(l*3 + 0)*C_DIM,
                                                  ln_b + (size_t)(l*3 + 0)*C_DIM, OT, OTh);

        // ---- cross attention (Q from OT=x1, K/V from LI=layer input) ----
        bgemm_t<1><<<dim3(256/128, MB), 256>>>(OTh, C_DIM, w_caw, C_DIM,
                                               ca_b + (size_t)l*768, qkv, 768, C_DIM, 0);
        bgemm_t<1><<<dim3(512/128, MB), 256>>>(LIh, C_DIM, w_caw + 256*256, C_DIM,
                                               ca_b + (size_t)l*768 + 256, qkv + 256, 768, C_DIM, 0);
        attn_bf16_kernel<<<attn_grid, 128, ATT_SMEM_BYTES>>>(qkv, att);
        bgemm_t<0><<<dim3(256/128, MB), 256>>>(att, C_DIM, w_caow, C_DIM,
                                               ca_ob + (size_t)l*256, proj, 256, C_DIM, 0);
        add_ln_kernel<<<M_TOTAL/4, dim3(64, 4)>>>(OT, proj,
                                                  ln_g + (size_t)(l*3 + 1)*C_DIM,
                                                  ln_b + (size_t)(l*3 + 1)*C_DIM, LI, LIh);

        // ---- FFN ----
        bgemm_t<1><<<dim3(FF_DIM/128, MB), 256>>>(LIh, C_DIM, w_ff1, C_DIM,
                                                  b1f + (size_t)l*FF_DIM, h, FF_DIM, C_DIM, 1);
        bgemm_t<0><<<dim3(256/128, MB), 256>>>(h, FF_DIM, w_ff2, FF_DIM,
                                               b2f + (size_t)l*256, proj, 256, FF_DIM, 0);
        add_ln_kernel<<<M_TOTAL/4, dim3(64, 4)>>>(LI, proj,
                                                  ln_g + (size_t)(l*3 + 2)*C_DIM,
                                                  ln_b + (size_t)(l*3 + 2)*C_DIM, OT, OTh);

        float* t0 = LI; LI = OT; OT = t0;
        bf16*  t1 = LIh; LIh = OTh; OTh = t1;
    }

    final_out_kernel<<<dim3(128, 8, 4), dim3(32, 8)>>>(LI, (float*)d_out);
}

// round 15
// speedup vs baseline: 1.0488x; 1.0092x over previous
#include <cuda_runtime.h>
#include <cuda_bf16.h>
#include <math.h>
#include <stdint.h>

// Problem constants
#define B_SZ     4
#define C_DIM    256
#define T_LEN    4096
#define FF_DIM   1024
#define NLAYERS  2
#define CHUNK    128
#define S_LEN    384          // 3*CHUNK
#define NW       32           // T/CHUNK
#define NSEQ     128          // B*NW
#define M_TOTAL  49152        // NSEQ*S_LEN
#define NHEADS   8
#define DH       32
#define EPS      1e-5f

typedef __nv_bfloat16  bf16;
typedef __nv_bfloat162 bf162;

// ---------------------------------------------------------------------------
// Device scratch
// ---------------------------------------------------------------------------
__device__ float g_bufA [M_TOTAL * C_DIM];
__device__ float g_bufB [M_TOTAL * C_DIM];
__device__ float g_proj [M_TOTAL * C_DIM];
__device__ bf16  g_bufAh[M_TOTAL * C_DIM];
__device__ bf16  g_bufBh[M_TOTAL * C_DIM];
__device__ bf16  g_qkv  [M_TOTAL * 768];
__device__ bf16  g_att  [M_TOTAL * C_DIM];
__device__ bf16  g_h    [M_TOTAL * FF_DIM];
__device__ bf16  g_wbf  [2097152];

#define OFF_SAW   0
#define OFF_SAOW  393216
#define OFF_CAW   524288
#define OFF_CAOW  917504
#define OFF_W1    1048576
#define OFF_W2    1572864

// ---------------------------------------------------------------------------
// helpers
// ---------------------------------------------------------------------------
__device__ __forceinline__ uint32_t packbf(float x, float y)
{
    bf162 h = __floats2bfloat162_rn(x, y);
    return *(uint32_t*)&h;
}

__device__ __forceinline__ void mma_bf16(float* c, const uint32_t* a, const uint32_t* b)
{
    asm volatile("mma.sync.aligned.m16n8k16.row.col.f32.bf16.bf16.f32 "
                 "{%0,%1,%2,%3}, {%4,%5,%6,%7}, {%8,%9}, {%0,%1,%2,%3};"
                 : "+f"(c[0]), "+f"(c[1]), "+f"(c[2]), "+f"(c[3])
                 : "r"(a[0]), "r"(a[1]), "r"(a[2]), "r"(a[3]),
                   "r"(b[0]), "r"(b[1]));
}

__device__ __forceinline__ void ldsm_x4b(uint32_t* d, const bf16* p)
{
    uint32_t a = (uint32_t)__cvta_generic_to_shared(p);
    asm volatile("ldmatrix.sync.aligned.m8n8.x4.shared.b16 {%0,%1,%2,%3}, [%4];"
                 : "=r"(d[0]), "=r"(d[1]), "=r"(d[2]), "=r"(d[3]) : "r"(a));
}

__device__ __forceinline__ void cp16(bf16* dst, const bf16* src)
{
    uint32_t d = (uint32_t)__cvta_generic_to_shared(dst);
    asm volatile("cp.async.ca.shared.global [%0], [%1], 16;" :: "r"(d), "l"(src));
}
#define CP_COMMIT() asm volatile("cp.async.commit_group;")
#define CP_WAIT0()  asm volatile("cp.async.wait_group 0;")

// ---------------------------------------------------------------------------
// Weight fp32 -> bf16 conversion
// ---------------------------------------------------------------------------
__global__ void convert_w_kernel(const float* __restrict__ src, bf16* __restrict__ dst, int n4)
{
    int i = blockIdx.x * blockDim.x + threadIdx.x;
    if (i < n4) {
        float4 v = ((const float4*)src)[i];
        bf162 a = __floats2bfloat162_rn(v.x, v.y);
        bf162 b = __floats2bfloat162_rn(v.z, v.w);
        ((bf162*)dst)[2 * i]     = a;
        ((bf162*)dst)[2 * i + 1] = b;
    }
}

__global__ void convert_w2_kernel(const float* __restrict__ s0, bf16* __restrict__ d0, int n40,
                                  const float* __restrict__ s1, bf16* __restrict__ d1, int n41)
{
    int i = blockIdx.x * blockDim.x + threadIdx.x;
    const float* src = blockIdx.y ? s1 : s0;
    bf16*        dst = blockIdx.y ? d1 : d0;
    int          n4  = blockIdx.y ? n41 : n40;
    if (i < n4) {
        float4 v = ((const float4*)src)[i];
        bf162 a = __floats2bfloat162_rn(v.x, v.y);
        bf162 b = __floats2bfloat162_rn(v.z, v.w);
        ((bf162*)dst)[2 * i]     = a;
        ((bf162*)dst)[2 * i + 1] = b;
    }
}

// ---------------------------------------------------------------------------
// build_x
// ---------------------------------------------------------------------------
__global__ void build_x_kernel(const float* __restrict__ mem, float* __restrict__ x,
                               bf16* __restrict__ xh)
{
    __shared__ float tile[32][33];
    int p0 = blockIdx.x * 32, c0 = blockIdx.y * 32, seq = blockIdx.z;
    int b = seq >> 5, w = seq & 31;
    int tx = threadIdx.x, ty = threadIdx.y;
    int t_off = w * CHUNK + p0 - CHUNK;
    #pragma unroll
    for (int i = ty; i < 32; i += 8) {
        int tpos = t_off + tx;
        float v = 0.f;
        if (tpos >= 0 && tpos < T_LEN)
            v = mem[((size_t)b * C_DIM + c0 + i) * T_LEN + tpos];
        tile[i][tx] = v;
    }
    __syncthreads();
    #pragma unroll
    for (int i = ty; i < 32; i += 8) {
        int p = p0 + i;
        int c = c0 + tx;
        int j = c >> 1;
        float dv  = __expf((float)(2 * j) * (-9.210340371976184f / (float)C_DIM));
        float ang = (float)p * dv;
        float pe  = (c & 1) ? cosf(ang) : sinf(ang);
        float val = tile[tx][i] + pe;
        size_t idx = ((size_t)seq * S_LEN + p) * C_DIM + c;
        x[idx]  = val;
        xh[idx] = __float2bfloat16_rn(val);
    }
}

// ---------------------------------------------------------------------------
// bf16 GEMM with cp.async staging.
//   C[m,n] = sum_k A[m,k]*W[n,k] + bias[n] (+ReLU) (+xres residual if non-null)
// Dual-A: blocks with bn >= bnSplit read A2 instead of A (same lda).
// Block 128x128, BK=32, 8 warps 2x4, warp 64x32. smem stride 40 bf16.
// ---------------------------------------------------------------------------
#define GSTR 40
template<int CBF16>
__global__ __launch_bounds__(256, 2)
void bgemm_t(const bf16* __restrict__ A, const bf16* __restrict__ A2, int bnSplit,
             int lda,
             const bf16* __restrict__ W, int ldw,
             const float* __restrict__ bias,
             const float* __restrict__ xres,          // may be null; fp32 [M, ldc]
             void* __restrict__ Cv, int ldc,
             int K, int doRelu)
{
    __shared__ __align__(16) bf16 As[2][128 * GSTR];
    __shared__ __align__(16) bf16 Bs[2][128 * GSTR];

    int tid  = threadIdx.x;
    int lane = tid & 31;
    int warp = tid >> 5;
    int wm = warp & 1;
    int wn = warp >> 1;
    int bm = blockIdx.y, bn = blockIdx.x;
    int r  = lane >> 2;
    int cc = lane & 3;

    const bf16* Abase = (bn >= bnSplit) ? A2 : A;

    int srow = tid & 127;
    int soff = (tid >> 7) * 16;
    const bf16* Ap = Abase + (size_t)(bm * 128 + srow) * lda + soff;
    const bf16* Wp = W + (size_t)(bn * 128 + srow) * ldw + soff;

    int a_row = wm * 64 + (lane & 15);
    int a_col = ((lane >> 4) & 1) * 8;
    int b_row = wn * 32 + (lane >> 4) * 8 + (lane & 7);
    int b_col = ((lane >> 3) & 1) * 8;

    float acc[4][4][4];
    #pragma unroll
    for (int i = 0; i < 4; i++)
        #pragma unroll
        for (int j = 0; j < 4; j++)
            #pragma unroll
            for (int q = 0; q < 4; q++) acc[i][j][q] = 0.f;

    // stage k-tile 0
    cp16(&As[0][srow * GSTR + soff],     Ap);
    cp16(&As[0][srow * GSTR + soff + 8], Ap + 8);
    cp16(&Bs[0][srow * GSTR + soff],     Wp);
    cp16(&Bs[0][srow * GSTR + soff + 8], Wp + 8);
    CP_COMMIT();

    int niter = K >> 5;
    for (int it = 0; it < niter; it++) {
        int cur = it & 1;
        CP_WAIT0();
        __syncthreads();
        if (it + 1 < niter) {
            int nxt = cur ^ 1;
            const bf16* An = Ap + (it + 1) * 32;
            const bf16* Wn = Wp + (it + 1) * 32;
            cp16(&As[nxt][srow * GSTR + soff],     An);
            cp16(&As[nxt][srow * GSTR + soff + 8], An + 8);
            cp16(&Bs[nxt][srow * GSTR + soff],     Wn);
            cp16(&Bs[nxt][srow * GSTR + soff + 8], Wn + 8);
            CP_COMMIT();
        }

        const bf16* Ac = As[cur];
        const bf16* Bc = Bs[cur];
        #pragma unroll
        for (int kb = 0; kb < 2; kb++) {
            uint32_t af[4][4];
            uint32_t bfr[4][2];
            #pragma unroll
            for (int mt = 0; mt < 4; mt++)
                ldsm_x4b(af[mt], Ac + (a_row + mt * 16) * GSTR + kb * 16 + a_col);
            #pragma unroll
            for (int np = 0; np < 2; np++) {
                uint32_t t4[4];
                ldsm_x4b(t4, Bc + (b_row + np * 16) * GSTR + kb * 16 + b_col);
                bfr[2 * np][0]     = t4[0];
                bfr[2 * np][1]     = t4[1];
                bfr[2 * np + 1][0] = t4[2];
                bfr[2 * np + 1][1] = t4[3];
            }
            #pragma unroll
            for (int mt = 0; mt < 4; mt++)
                #pragma unroll
                for (int nt = 0; nt < 4; nt++)
                    mma_bf16(acc[mt][nt], af[mt], bfr[nt]);
        }
    }

    int c2 = cc * 2;
    #pragma unroll
    for (int mt = 0; mt < 4; mt++) {
        int row0 = bm * 128 + wm * 64 + mt * 16 + r;
        #pragma unroll
        for (int nt = 0; nt < 4; nt++) {
            int col = bn * 128 + wn * 32 + nt * 8 + c2;
            float bx = bias[col], by = bias[col + 1];
            float2 v0, v1;
            v0.x = acc[mt][nt][0] + bx; v0.y = acc[mt][nt][1] + by;
            v1.x = acc[mt][nt][2] + bx; v1.y = acc[mt][nt][3] + by;
            if (doRelu) {
                v0.x = fmaxf(v0.x, 0.f); v0.y = fmaxf(v0.y, 0.f);
                v1.x = fmaxf(v1.x, 0.f); v1.y = fmaxf(v1.y, 0.f);
            }
            if (xres) {
                float2 x0 = *(const float2*)(xres + (size_t)row0 * ldc + col);
                float2 x1 = *(const float2*)(xres + (size_t)(row0 + 8) * ldc + col);
                v0.x += x0.x; v0.y += x0.y;
                v1.x += x1.x; v1.y += x1.y;
            }
            if (CBF16) {
                bf16* Cp = (bf16*)Cv;
                *(bf162*)(Cp + (size_t)row0 * ldc + col)       = __float22bfloat162_rn(v0);
                *(bf162*)(Cp + (size_t)(row0 + 8) * ldc + col) = __float22bfloat162_rn(v1);
            } else {
                float* Cp = (float*)Cv;
                *(float2*)(Cp + (size_t)row0 * ldc + col)       = v0;
                *(float2*)(Cp + (size_t)(row0 + 8) * ldc + col) = v1;
            }
        }
    }
}

// ---------------------------------------------------------------------------
// bf16 MMA flash attention (R14 shape, unchanged).
// ---------------------------------------------------------------------------
#define KSB  40
#define VST  392
#define ATT_SMEM_BYTES ((S_LEN * KSB + DH * VST) * (int)sizeof(bf16))   // 55808

__global__ __launch_bounds__(128, 4)
void attn_bf16_kernel(const bf16* __restrict__ qkv, bf16* __restrict__ att)
{
    extern __shared__ __align__(16) bf16 smb[];
    bf16* Ks = smb;
    bf16* Vs = smb + S_LEN * KSB;

    int tid  = threadIdx.x;
    int lane = tid & 31, warp = tid >> 5;
    int r = lane >> 2, cc = lane & 3;
    int seq = blockIdx.x, h = blockIdx.y;
    const bf16* base = qkv + (size_t)seq * S_LEN * 768;

    int brow = (lane & 7) + ((lane >> 4) & 1) * 8;
    int bcol = ((lane >> 3) & 1) * 8;

    #pragma unroll
    for (int i = 0; i < 6; i++) {
        int lin = i * 128 + tid;
        int key = lin >> 1;
        int ch  = (lin & 1) * 16;
        const bf16* src = base + (size_t)key * 768 + 256 + h * DH + ch;
        uint4 k0 = *(const uint4*)src;
        uint4 k1 = *(const uint4*)(src + 8);
        *(uint4*)&Ks[key * KSB + ch]     = k0;
        *(uint4*)&Ks[key * KSB + ch + 8] = k1;
    }
    #pragma unroll
    for (int i = 0; i < 6; i++) {
        int kp  = tid & 31;
        int oct = tid >> 5;
        int keyb = i * 64 + 2 * kp;
        const bf16* v0 = base + (size_t)keyb * 768 + 512 + h * DH + oct * 8;
        uint4 ra = *(const uint4*)v0;
        uint4 rb = *(const uint4*)(v0 + 768);
        const bf16* va = (const bf16*)&ra;
        const bf16* vb = (const bf16*)&rb;
        #pragma unroll
        for (int d = 0; d < 8; d++) {
            bf162 pr;
            pr.x = va[d]; pr.y = vb[d];
            *(bf162*)&Vs[(oct * 8 + d) * VST + keyb] = pr;
        }
    }
    __syncthreads();

    for (int qc = 0; qc < 3; qc++) {
        int qbase = qc * 128 + warp * 32;

        uint32_t qa[2][2][4];
        #pragma unroll
        for (int mt = 0; mt < 2; mt++) {
            const bf16* q0 = base + (size_t)(qbase + mt * 16 + r) * 768 + h * DH;
            const bf16* q1 = q0 + 8 * 768;
            const float sc = 0.17677669529663687f;
            #pragma unroll
            for (int kb = 0; kb < 2; kb++) {
                bf162 p00 = *(const bf162*)(q0 + kb * 16 + 2 * cc);
                bf162 p01 = *(const bf162*)(q0 + kb * 16 + 2 * cc + 8);
                bf162 p10 = *(const bf162*)(q1 + kb * 16 + 2 * cc);
                bf162 p11 = *(const bf162*)(q1 + kb * 16 + 2 * cc + 8);
                float2 f;
                f = __bfloat1622float2(p00); qa[mt][kb][0] = packbf(f.x * sc, f.y * sc);
                f = __bfloat1622float2(p10); qa[mt][kb][1] = packbf(f.x * sc, f.y * sc);
                f = __bfloat1622float2(p01); qa[mt][kb][2] = packbf(f.x * sc, f.y * sc);
                f = __bfloat1622float2(p11); qa[mt][kb][3] = packbf(f.x * sc, f.y * sc);
            }
        }

        float lrun[2][2], oacc[2][4][4];
        #pragma unroll
        for (int mt = 0; mt < 2; mt++) {
            lrun[mt][0] = 0.f; lrun[mt][1] = 0.f;
            #pragma unroll
            for (int nt = 0; nt < 4; nt++)
                #pragma unroll
                for (int q = 0; q < 4; q++) oacc[mt][nt][q] = 0.f;
        }

        for (int kt = 0; kt < 12; kt++) {
            int kt32 = kt * 32;

            float sacc[2][4][4];
            #pragma unroll
            for (int mt = 0; mt < 2; mt++)
                #pragma unroll
                for (int nt = 0; nt < 4; nt++)
                    #pragma unroll
                    for (int q = 0; q < 4; q++) sacc[mt][nt][q] = 0.f;

            #pragma unroll
            for (int kb = 0; kb < 2; kb++) {
                #pragma unroll
                for (int kq = 0; kq < 2; kq++) {
                    uint32_t t4[4];
                    ldsm_x4b(t4, Ks + (kt32 + kq * 16 + brow) * KSB + kb * 16 + bcol);
                    #pragma unroll
                    for (int mt = 0; mt < 2; mt++) {
                        mma_bf16(sacc[mt][2 * kq],     qa[mt][kb], t4);
                        mma_bf16(sacc[mt][2 * kq + 1], qa[mt][kb], t4 + 2);
                    }
                }
            }

            #pragma unroll
            for (int kg = 0; kg < 2; kg++) {
                uint32_t bv[4][2];
                #pragma unroll
                for (int np = 0; np < 2; np++) {
                    uint32_t t4[4];
                    ldsm_x4b(t4, Vs + (np * 16 + brow) * VST + kt32 + kg * 16 + bcol);
                    bv[2 * np][0]     = t4[0];
                    bv[2 * np][1]     = t4[1];
                    bv[2 * np + 1][0] = t4[2];
                    bv[2 * np + 1][1] = t4[3];
                }
                #pragma unroll
                for (int mt = 0; mt < 2; mt++) {
                    float e0 = __expf(sacc[mt][2 * kg][0]);
                    float e1 = __expf(sacc[mt][2 * kg][1]);
                    float e2 = __expf(sacc[mt][2 * kg][2]);
                    float e3 = __expf(sacc[mt][2 * kg][3]);
                    float e4 = __expf(sacc[mt][2 * kg + 1][0]);
                    float e5 = __expf(sacc[mt][2 * kg + 1][1]);
                    float e6 = __expf(sacc[mt][2 * kg + 1][2]);
                    float e7 = __expf(sacc[mt][2 * kg + 1][3]);
                    lrun[mt][0] += e0 + e1 + e4 + e5;
                    lrun[mt][1] += e2 + e3 + e6 + e7;
                    uint32_t af[4];
                    af[0] = packbf(e0, e1);
                    af[1] = packbf(e2, e3);
                    af[2] = packbf(e4, e5);
                    af[3] = packbf(e6, e7);
                    #pragma unroll
                    for (int nt = 0; nt < 4; nt++)
                        mma_bf16(oacc[mt][nt], af, bv[nt]);
                }
            }
        }

        #pragma unroll
        for (int mt = 0; mt < 2; mt++) {
            float l0 = lrun[mt][0];
            l0 += __shfl_xor_sync(0xFFFFFFFFu, l0, 1);
            l0 += __shfl_xor_sync(0xFFFFFFFFu, l0, 2);
            float l1 = lrun[mt][1];
            l1 += __shfl_xor_sync(0xFFFFFFFFu, l1, 1);
            l1 += __shfl_xor_sync(0xFFFFFFFFu, l1, 2);
            float inv0 = 1.f / l0, inv1 = 1.f / l1;
            size_t grow = (size_t)seq * S_LEN + qbase + mt * 16 + r;
            #pragma unroll
            for (int nt = 0; nt < 4; nt++) {
                int col = h * DH + nt * 8 + 2 * cc;
                float2 v0, v1;
                v0.x = oacc[mt][nt][0] * inv0; v0.y = oacc[mt][nt][1] * inv0;
                v1.x = oacc[mt][nt][2] * inv1; v1.y = oacc[mt][nt][3] * inv1;
                *(bf162*)(att + grow * C_DIM + col)       = __float22bfloat162_rn(v0);
                *(bf162*)(att + (grow + 8) * C_DIM + col) = __float22bfloat162_rn(v1);
            }
        }
    }
}

// ---------------------------------------------------------------------------
// LayerNorm on precomputed v (= x + sub + bias); writes fp32 + bf16 mirror.
// ---------------------------------------------------------------------------
__global__ void ln_kernel(const float* __restrict__ vin,
                          const float* __restrict__ g, const float* __restrict__ b,
                          float* __restrict__ out, bf16* __restrict__ outh)
{
    int tx = threadIdx.x, ty = threadIdx.y;
    int row = blockIdx.x * 4 + ty;
    size_t base = (size_t)row * C_DIM + tx * 4;
    float4 v = *(const float4*)(vin + base);
    float s  = v.x + v.y + v.z + v.w;
    float s2 = v.x * v.x + v.y * v.y + v.z * v.z + v.w * v.w;
    #pragma unroll
    for (int off = 16; off; off >>= 1) {
        s  += __shfl_xor_sync(0xFFFFFFFFu, s,  off);
        s2 += __shfl_xor_sync(0xFFFFFFFFu, s2, off);
    }
    __shared__ float red[4][2][2];
    int wh = tx >> 5;
    if ((tx & 31) == 0) { red[ty][wh][0] = s; red[ty][wh][1] = s2; }
    __syncthreads();
    float ts  = red[ty][0][0] + red[ty][1][0];
    float ts2 = red[ty][0][1] + red[ty][1][1];
    float mean = ts * (1.f / C_DIM);
    float var  = ts2 * (1.f / C_DIM) - mean * mean;
    float rstd = rsqrtf(var + EPS);
    float4 gv = *(const float4*)(g + tx * 4);
    float4 bv = *(const float4*)(b + tx * 4);
    float4 o;
    o.x = (v.x - mean) * rstd * gv.x + bv.x;
    o.y = (v.y - mean) * rstd * gv.y + bv.y;
    o.z = (v.z - mean) * rstd * gv.z + bv.z;
    o.w = (v.w - mean) * rstd * gv.w + bv.w;
    *(float4*)(out + base) = o;
    bf162 h0 = __floats2bfloat162_rn(o.x, o.y);
    bf162 h1 = __floats2bfloat162_rn(o.z, o.w);
    uint2 pk;
    pk.x = *(uint32_t*)&h0;
    pk.y = *(uint32_t*)&h1;
    *(uint2*)(outh + base) = pk;
}

// ---------------------------------------------------------------------------
// Final gather
// ---------------------------------------------------------------------------
__global__ void final_out_kernel(const float* __restrict__ x, float* __restrict__ out)
{
    __shared__ float tile[32][33];
    int t0 = blockIdx.x * 32, c0 = blockIdx.y * 32, b = blockIdx.z;
    int tx = threadIdx.x, ty = threadIdx.y;
    #pragma unroll
    for (int i = ty; i < 32; i += 8) {
        int t = t0 + i;
        size_t row = (size_t)(b * NW + (t >> 7)) * S_LEN + CHUNK + (t & 127);
        tile[i][tx] = x[row * C_DIM + c0 + tx];
    }
    __syncthreads();
    #pragma unroll
    for (int i = ty; i < 32; i += 8)
        out[((size_t)b * C_DIM + c0 + i) * T_LEN + t0 + tx] = tile[tx][i];
}

// ---------------------------------------------------------------------------
// Host orchestration. Attention remains my launch #3 (process launch 5).
// ---------------------------------------------------------------------------
extern "C" void kernel_launch(void* const* d_in, const int* in_sizes, int n_in,
                              void* d_out, int out_size)
{
    (void)in_sizes; (void)n_in; (void)out_size;
    const float* mem   = (const float*)d_in[0];
    const float* sa_w  = (const float*)d_in[1];
    const float* sa_b  = (const float*)d_in[2];
    const float* sa_ow = (const float*)d_in[3];
    const float* sa_ob = (const float*)d_in[4];
    const float* ca_w  = (const float*)d_in[5];
    const float* ca_b  = (const float*)d_in[6];
    const float* ca_ow = (const float*)d_in[7];
    const float* ca_ob = (const float*)d_in[8];
    const float* w1    = (const float*)d_in[9];
    const float* b1f   = (const float*)d_in[10];
    const float* w2    = (const float*)d_in[11];
    const float* b2f   = (const float*)d_in[12];
    const float* ln_g  = (const float*)d_in[13];
    const float* ln_b  = (const float*)d_in[14];

    float *bufA, *bufB, *proj;
    bf16 *bufAh, *bufBh, *qkv, *att, *h, *wbf;
    cudaGetSymbolAddress((void**)&bufA,  g_bufA);
    cudaGetSymbolAddress((void**)&bufB,  g_bufB);
    cudaGetSymbolAddress((void**)&proj,  g_proj);
    cudaGetSymbolAddress((void**)&bufAh, g_bufAh);
    cudaGetSymbolAddress((void**)&bufBh, g_bufBh);
    cudaGetSymbolAddress((void**)&qkv,   g_qkv);
    cudaGetSymbolAddress((void**)&att,   g_att);
    cudaGetSymbolAddress((void**)&h,     g_h);
    cudaGetSymbolAddress((void**)&wbf,   g_wbf);

    cudaFuncSetAttribute(attn_bf16_kernel, cudaFuncAttributeMaxDynamicSharedMemorySize,
                         ATT_SMEM_BYTES);

    const int MB = M_TOTAL / 128;   // 384
    dim3 attn_grid(NSEQ, NHEADS);
    const int BIG = 1 << 20;

    float* LI = bufA;   bf16* LIh = bufAh;
    float* OT = bufB;   bf16* OTh = bufBh;

    // my-launch 0: convert sa_w; my-launch 1: build x
    convert_w_kernel<<< 384, 256>>>(sa_w, wbf + OFF_SAW, 98304);
    build_x_kernel<<<dim3(12, 8, NSEQ), dim3(32, 8)>>>(mem, bufA, bufAh);

    for (int l = 0; l < NLAYERS; l++) {
        const bf16* w_qkv  = wbf + OFF_SAW  + (size_t)l * 196608;
        const bf16* w_saow = wbf + OFF_SAOW + (size_t)l * 65536;
        const bf16* w_caw  = wbf + OFF_CAW  + (size_t)l * 196608;
        const bf16* w_caow = wbf + OFF_CAOW + (size_t)l * 65536;
        const bf16* w_ff1  = wbf + OFF_W1   + (size_t)l * 262144;
        const bf16* w_ff2  = wbf + OFF_W2   + (size_t)l * 262144;

        // ---- self attention ---- (l=0: my launches 2, 3)
        bgemm_t<1><<<dim3(768/128, MB), 256>>>(LIh, LIh, BIG, C_DIM, w_qkv, C_DIM,
                                               sa_b + (size_t)l*768, nullptr, qkv, 768, C_DIM, 0);
        attn_bf16_kernel<<<attn_grid, 128, ATT_SMEM_BYTES>>>(qkv, att);

        if (l == 0) {
            convert_w2_kernel<<<dim3(384, 2), 256>>>(sa_ow, wbf + OFF_SAOW, 32768,
                                                     ca_w,  wbf + OFF_CAW,  98304);
            convert_w2_kernel<<<dim3(512, 2), 256>>>(ca_ow, wbf + OFF_CAOW, 32768,
                                                     w1,    wbf + OFF_W1,  131072);
            convert_w_kernel<<< 512, 256>>>(w2, wbf + OFF_W2, 131072);
        }

        // sa out-proj + residual fused; then LN
        bgemm_t<0><<<dim3(256/128, MB), 256>>>(att, att, BIG, C_DIM, w_saow, C_DIM,
                                               sa_ob + (size_t)l*256, LI, proj, 256, C_DIM, 0);
        ln_kernel<<<M_TOTAL/4, dim3(64, 4)>>>(proj,
                                              ln_g + (size_t)(l*3 + 0)*C_DIM,
                                              ln_b + (size_t)(l*3 + 0)*C_DIM, OT, OTh);

        // ---- cross attention: merged Q-proj (A=OTh, bn 0..1) + KV-proj (A=LIh, bn 2..5) ----
        bgemm_t<1><<<dim3(768/128, MB), 256>>>(OTh, LIh, 2, C_DIM, w_caw, C_DIM,
                                               ca_b + (size_t)l*768, nullptr, qkv, 768, C_DIM, 0);
        attn_bf16_kernel<<<attn_grid, 128, ATT_SMEM_BYTES>>>(qkv, att);
        bgemm_t<0><<<dim3(256/128, MB), 256>>>(att, att, BIG, C_DIM, w_caow, C_DIM,
                                               ca_ob + (size_t)l*256, OT, proj, 256, C_DIM, 0);
        ln_kernel<<<M_TOTAL/4, dim3(64, 4)>>>(proj,
                                              ln_g + (size_t)(l*3 + 1)*C_DIM,
                                              ln_b + (size_t)(l*3 + 1)*C_DIM, LI, LIh);

        // ---- FFN ----
        bgemm_t<1><<<dim3(FF_DIM/128, MB), 256>>>(LIh, LIh, BIG, C_DIM, w_ff1, C_DIM,
                                                  b1f + (size_t)l*FF_DIM, nullptr, h, FF_DIM, C_DIM, 1);
        bgemm_t<0><<<dim3(256/128, MB), 256>>>(h, h, BIG, FF_DIM, w_ff2, FF_DIM,
                                               b2f + (size_t)l*256, LI, proj, 256, FF_DIM, 0);
        ln_kernel<<<M_TOTAL/4, dim3(64, 4)>>>(proj,
                                              ln_g + (size_t)(l*3 + 2)*C_DIM,
                                              ln_b + (size_t)(l*3 + 2)*C_DIM, OT, OTh);

        float* t0 = LI; LI = OT; OT = t0;
        bf16*  t1 = LIh; LIh = OTh; OTh = t1;
    }

    final_out_kernel<<<dim3(128, 8, 4), dim3(32, 8)>>>(LI, (float*)d_out);
}

// round 16
// speedup vs baseline: 1.0734x; 1.0234x over previous
#include <cuda_runtime.h>
#include <cuda_bf16.h>
#include <math.h>
#include <stdint.h>

#define B_SZ     4
#define C_DIM    256
#define T_LEN    4096
#define FF_DIM   1024
#define NLAYERS  2
#define CHUNK    128
#define S_LEN    384
#define NW       32
#define NSEQ     128
#define M_TOTAL  49152
#define NHEADS   8
#define DH       32
#define EPS      1e-5f

typedef __nv_bfloat16  bf16;
typedef __nv_bfloat162 bf162;

__device__ float g_bufA [M_TOTAL * C_DIM];
__device__ float g_bufB [M_TOTAL * C_DIM];
__device__ float g_proj [M_TOTAL * C_DIM];
__device__ bf16  g_bufAh[M_TOTAL * C_DIM];
__device__ bf16  g_bufBh[M_TOTAL * C_DIM];
__device__ bf16  g_qkv  [M_TOTAL * 768];
__device__ bf16  g_att  [M_TOTAL * C_DIM];
__device__ bf16  g_h    [M_TOTAL * FF_DIM];
__device__ bf16  g_wbf  [2097152];

#define OFF_SAW   0
#define OFF_SAOW  393216
#define OFF_CAW   524288
#define OFF_CAOW  917504
#define OFF_W1    1048576
#define OFF_W2    1572864

__device__ __forceinline__ uint32_t packbf(float x, float y)
{
    bf162 h = __floats2bfloat162_rn(x, y);
    return *(uint32_t*)&h;
}

__device__ __forceinline__ float ex2f(float x)
{
    float r;
    asm("ex2.approx.ftz.f32 %0, %1;" : "=f"(r) : "f"(x));
    return r;
}

__device__ __forceinline__ void mma_bf16(float* c, const uint32_t* a, const uint32_t* b)
{
    asm volatile("mma.sync.aligned.m16n8k16.row.col.f32.bf16.bf16.f32 "
                 "{%0,%1,%2,%3}, {%4,%5,%6,%7}, {%8,%9}, {%0,%1,%2,%3};"
                 : "+f"(c[0]), "+f"(c[1]), "+f"(c[2]), "+f"(c[3])
                 : "r"(a[0]), "r"(a[1]), "r"(a[2]), "r"(a[3]),
                   "r"(b[0]), "r"(b[1]));
}

__device__ __forceinline__ void ldsm_x4b(uint32_t* d, const bf16* p)
{
    uint32_t a = (uint32_t)__cvta_generic_to_shared(p);
    asm volatile("ldmatrix.sync.aligned.m8n8.x4.shared.b16 {%0,%1,%2,%3}, [%4];"
                 : "=r"(d[0]), "=r"(d[1]), "=r"(d[2]), "=r"(d[3]) : "r"(a));
}

__device__ __forceinline__ void cp16(bf16* dst, const bf16* src)
{
    uint32_t d = (uint32_t)__cvta_generic_to_shared(dst);
    asm volatile("cp.async.ca.shared.global [%0], [%1], 16;" :: "r"(d), "l"(src));
}
#define CP_COMMIT() asm volatile("cp.async.commit_group;")
#define CP_WAIT1()  asm volatile("cp.async.wait_group 1;")

__global__ void convert_w_kernel(const float* __restrict__ src, bf16* __restrict__ dst, int n4)
{
    int i = blockIdx.x * blockDim.x + threadIdx.x;
    if (i < n4) {
        float4 v = ((const float4*)src)[i];
        bf162 a = __floats2bfloat162_rn(v.x, v.y);
        bf162 b = __floats2bfloat162_rn(v.z, v.w);
        ((bf162*)dst)[2 * i]     = a;
        ((bf162*)dst)[2 * i + 1] = b;
    }
}

__global__ void convert_w2_kernel(const float* __restrict__ s0, bf16* __restrict__ d0, int n40,
                                  const float* __restrict__ s1, bf16* __restrict__ d1, int n41)
{
    int i = blockIdx.x * blockDim.x + threadIdx.x;
    const float* src = blockIdx.y ? s1 : s0;
    bf16*        dst = blockIdx.y ? d1 : d0;
    int          n4  = blockIdx.y ? n41 : n40;
    if (i < n4) {
        float4 v = ((const float4*)src)[i];
        bf162 a = __floats2bfloat162_rn(v.x, v.y);
        bf162 b = __floats2bfloat162_rn(v.z, v.w);
        ((bf162*)dst)[2 * i]     = a;
        ((bf162*)dst)[2 * i + 1] = b;
    }
}

__global__ void build_x_kernel(const float* __restrict__ mem, float* __restrict__ x,
                               bf16* __restrict__ xh)
{
    __shared__ float tile[32][33];
    int p0 = blockIdx.x * 32, c0 = blockIdx.y * 32, seq = blockIdx.z;
    int b = seq >> 5, w = seq & 31;
    int tx = threadIdx.x, ty = threadIdx.y;
    int t_off = w * CHUNK + p0 - CHUNK;
    #pragma unroll
    for (int i = ty; i < 32; i += 8) {
        int tpos = t_off + tx;
        float v = 0.f;
        if (tpos >= 0 && tpos < T_LEN)
            v = mem[((size_t)b * C_DIM + c0 + i) * T_LEN + tpos];
        tile[i][tx] = v;
    }
    __syncthreads();
    #pragma unroll
    for (int i = ty; i < 32; i += 8) {
        int p = p0 + i;
        int c = c0 + tx;
        int j = c >> 1;
        float dv  = __expf((float)(2 * j) * (-9.210340371976184f / (float)C_DIM));
        float ang = (float)p * dv;
        float pe  = (c & 1) ? cosf(ang) : sinf(ang);
        float val = tile[tx][i] + pe;
        size_t idx = ((size_t)seq * S_LEN + p) * C_DIM + c;
        x[idx]  = val;
        xh[idx] = __float2bfloat16_rn(val);
    }
}

#define GSTR 40
#define GEMM_STAGE (128 * GSTR)
#define GEMM_SMEM_BYTES (6 * GEMM_STAGE * (int)sizeof(bf16))

template<int CBF16>
__global__ __launch_bounds__(256, 2)
void bgemm_t(const bf16* __restrict__ A, const bf16* __restrict__ A2, int bnSplit,
             int lda,
             const bf16* __restrict__ W, int ldw,
             const float* __restrict__ bias,
             const float* __restrict__ xres,
             void* __restrict__ Cv, int ldc,
             int K, int doRelu)
{
    extern __shared__ __align__(16) bf16 gsm[];
    bf16* AsB = gsm;
    bf16* BsB = gsm + 3 * GEMM_STAGE;

    int tid  = threadIdx.x;
    int lane = tid & 31;
    int warp = tid >> 5;
    int wm = warp & 1;
    int wn = warp >> 1;
    int bm = blockIdx.y, bn = blockIdx.x;
    int r  = lane >> 2;
    int cc = lane & 3;

    const bf16* Abase = (bn >= bnSplit) ? A2 : A;

    int srow = tid & 127;
    int soff = (tid >> 7) * 16;
    const bf16* Ap = Abase + (size_t)(bm * 128 + srow) * lda + soff;
    const bf16* Wp = W + (size_t)(bn * 128 + srow) * ldw + soff;

    int a_row = wm * 64 + (lane & 15);
    int a_col = ((lane >> 4) & 1) * 8;
    int b_row = wn * 32 + (lane >> 4) * 8 + (lane & 7);
    int b_col = ((lane >> 3) & 1) * 8;

    float acc[4][4][4];
    #pragma unroll
    for (int i = 0; i < 4; i++)
        #pragma unroll
        for (int j = 0; j < 4; j++)
            #pragma unroll
            for (int q = 0; q < 4; q++) acc[i][j][q] = 0.f;

    int niter = K >> 5;
    {
        bf16* as = AsB;
        bf16* bs = BsB;
        cp16(as + srow * GSTR + soff,     Ap);
        cp16(as + srow * GSTR + soff + 8, Ap + 8);
        cp16(bs + srow * GSTR + soff,     Wp);
        cp16(bs + srow * GSTR + soff + 8, Wp + 8);
        CP_COMMIT();
    }
    if (niter > 1) {
        bf16* as = AsB + GEMM_STAGE;
        bf16* bs = BsB + GEMM_STAGE;
        cp16(as + srow * GSTR + soff,     Ap + 32);
        cp16(as + srow * GSTR + soff + 8, Ap + 40);
        cp16(bs + srow * GSTR + soff,     Wp + 32);
        cp16(bs + srow * GSTR + soff + 8, Wp + 40);
    }
    CP_COMMIT();

    for (int it = 0; it < niter; it++) {
        CP_WAIT1();
        __syncthreads();
        if (it + 2 < niter) {
            int s = (it + 2) % 3;
            bf16* as = AsB + s * GEMM_STAGE;
            bf16* bs = BsB + s * GEMM_STAGE;
            const bf16* An = Ap + (it + 2) * 32;
            const bf16* Wn = Wp + (it + 2) * 32;
            cp16(as + srow * GSTR + soff,     An);
            cp16(as + srow * GSTR + soff + 8, An + 8);
            cp16(bs + srow * GSTR + soff,     Wn);
            cp16(bs + srow * GSTR + soff + 8, Wn + 8);
        }
        CP_COMMIT();

        const bf16* Ac = AsB + (it % 3) * GEMM_STAGE;
        const bf16* Bc = BsB + (it % 3) * GEMM_STAGE;
        #pragma unroll
        for (int kb = 0; kb < 2; kb++) {
            uint32_t af[4][4];
            uint32_t bfr[4][2];
            #pragma unroll
            for (int mt = 0; mt < 4; mt++)
                ldsm_x4b(af[mt], Ac + (a_row + mt * 16) * GSTR + kb * 16 + a_col);
            #pragma unroll
            for (int np = 0; np < 2; np++) {
                uint32_t t4[4];
                ldsm_x4b(t4, Bc + (b_row + np * 16) * GSTR + kb * 16 + b_col);
                bfr[2 * np][0]     = t4[0];
                bfr[2 * np][1]     = t4[1];
                bfr[2 * np + 1][0] = t4[2];
                bfr[2 * np + 1][1] = t4[3];
            }
            #pragma unroll
            for (int mt = 0; mt < 4; mt++)
                #pragma unroll
                for (int nt = 0; nt < 4; nt++)
                    mma_bf16(acc[mt][nt], af[mt], bfr[nt]);
        }
        __syncthreads();
    }

    int c2 = cc * 2;
    #pragma unroll
    for (int mt = 0; mt < 4; mt++) {
        int row0 = bm * 128 + wm * 64 + mt * 16 + r;
        #pragma unroll
        for (int nt = 0; nt < 4; nt++) {
            int col = bn * 128 + wn * 32 + nt * 8 + c2;
            float bx = bias[col], by = bias[col + 1];
            float2 v0, v1;
            v0.x = acc[mt][nt][0] + bx; v0.y = acc[mt][nt][1] + by;
            v1.x = acc[mt][nt][2] + bx; v1.y = acc[mt][nt][3] + by;
            if (doRelu) {
                v0.x = fmaxf(v0.x, 0.f); v0.y = fmaxf(v0.y, 0.f);
                v1.x = fmaxf(v1.x, 0.f); v1.y = fmaxf(v1.y, 0.f);
            }
            if (xres) {
                float2 x0 = *(const float2*)(xres + (size_t)row0 * ldc + col);
                float2 x1 = *(const float2*)(xres + (size_t)(row0 + 8) * ldc + col);
                v0.x += x0.x; v0.y += x0.y;
                v1.x += x1.x; v1.y += x1.y;
            }
            if (CBF16) {
                bf16* Cp = (bf16*)Cv;
                *(bf162*)(Cp + (size_t)row0 * ldc + col)       = __float22bfloat162_rn(v0);
                *(bf162*)(Cp + (size_t)(row0 + 8) * ldc + col) = __float22bfloat162_rn(v1);
            } else {
                float* Cp = (float*)Cv;
                *(float2*)(Cp + (size_t)row0 * ldc + col)       = v0;
                *(float2*)(Cp + (size_t)(row0 + 8) * ldc + col) = v1;
            }
        }
    }
}

#define KSB  40
#define VST  392
#define ATT_SMEM_BYTES ((S_LEN * KSB + DH * VST) * (int)sizeof(bf16))

__global__ __launch_bounds__(128, 4)
void attn_bf16_kernel(const bf16* __restrict__ qkv, bf16* __restrict__ att)
{
    extern __shared__ __align__(16) bf16 smb[];
    bf16* Ks = smb;
    bf16* Vs = smb + S_LEN * KSB;

    int tid  = threadIdx.x;
    int lane = tid & 31, warp = tid >> 5;
    int r = lane >> 2, cc = lane & 3;
    int seq = blockIdx.x, h = blockIdx.y;
    const bf16* base = qkv + (size_t)seq * S_LEN * 768;

    int brow = (lane & 7) + ((lane >> 4) & 1) * 8;
    int bcol = ((lane >> 3) & 1) * 8;

    #pragma unroll
    for (int i = 0; i < 6; i++) {
        int lin = i * 128 + tid;
        int key = lin >> 1;
        int ch  = (lin & 1) * 16;
        const bf16* src = base + (size_t)key * 768 + 256 + h * DH + ch;
        uint4 k0 = *(const uint4*)src;
        uint4 k1 = *(const uint4*)(src + 8);
        *(uint4*)&Ks[key * KSB + ch]     = k0;
        *(uint4*)&Ks[key * KSB + ch + 8] = k1;
    }
    #pragma unroll
    for (int i = 0; i < 6; i++) {
        int kp  = tid & 31;
        int oct = tid >> 5;
        int keyb = i * 64 + 2 * kp;
        const bf16* v0 = base + (size_t)keyb * 768 + 512 + h * DH + oct * 8;
        uint4 ra = *(const uint4*)v0;
        uint4 rb = *(const uint4*)(v0 + 768);
        const bf16* va = (const bf16*)&ra;
        const bf16* vb = (const bf16*)&rb;
        #pragma unroll
        for (int d = 0; d < 8; d++) {
            bf162 pr;
            pr.x = va[d]; pr.y = vb[d];
            *(bf162*)&Vs[(oct * 8 + d) * VST + keyb] = pr;
        }
    }
    __syncthreads();

    for (int qc = 0; qc < 3; qc++) {
        int qbase = qc * 128 + warp * 32;

        uint32_t qa[2][2][4];
        #pragma unroll
        for (int mt = 0; mt < 2; mt++) {
            const bf16* q0 = base + (size_t)(qbase + mt * 16 + r) * 768 + h * DH;
            const bf16* q1 = q0 + 8 * 768;
            const float sc = 0.2550557815f;   // (1/sqrt(32)) * log2(e); exp -> ex2
            #pragma unroll
            for (int kb = 0; kb < 2; kb++) {
                bf162 p00 = *(const bf162*)(q0 + kb * 16 + 2 * cc);
                bf162 p01 = *(const bf162*)(q0 + kb * 16 + 2 * cc + 8);
                bf162 p10 = *(const bf162*)(q1 + kb * 16 + 2 * cc);
                bf162 p11 = *(const bf162*)(q1 + kb * 16 + 2 * cc + 8);
                float2 f;
                f = __bfloat1622float2(p00); qa[mt][kb][0] = packbf(f.x * sc, f.y * sc);
                f = __bfloat1622float2(p10); qa[mt][kb][1] = packbf(f.x * sc, f.y * sc);
                f = __bfloat1622float2(p01); qa[mt][kb][2] = packbf(f.x * sc, f.y * sc);
                f = __bfloat1622float2(p11); qa[mt][kb][3] = packbf(f.x * sc, f.y * sc);
            }
        }

        float lrun[2][2], oacc[2][4][4];
        #pragma unroll
        for (int mt = 0; mt < 2; mt++) {
            lrun[mt][0] = 0.f; lrun[mt][1] = 0.f;
            #pragma unroll
            for (int nt = 0; nt < 4; nt++)
                #pragma unroll
                for (int q = 0; q < 4; q++) oacc[mt][nt][q] = 0.f;
        }

        for (int kt = 0; kt < 12; kt++) {
            int kt32 = kt * 32;

            float sacc[2][4][4];
            #pragma unroll
            for (int mt = 0; mt < 2; mt++)
                #pragma unroll
                for (int nt = 0; nt < 4; nt++)
                    #pragma unroll
                    for (int q = 0; q < 4; q++) sacc[mt][nt][q] = 0.f;

            #pragma unroll
            for (int kb = 0; kb < 2; kb++) {
                #pragma unroll
                for (int kq = 0; kq < 2; kq++) {
                    uint32_t t4[4];
                    ldsm_x4b(t4, Ks + (kt32 + kq * 16 + brow) * KSB + kb * 16 + bcol);
                    #pragma unroll
                    for (int mt = 0; mt < 2; mt++) {
                        mma_bf16(sacc[mt][2 * kq],     qa[mt][kb], t4);
                        mma_bf16(sacc[mt][2 * kq + 1], qa[mt][kb], t4 + 2);
                    }
                }
            }

            #pragma unroll
            for (int kg = 0; kg < 2; kg++) {
                uint32_t bv[4][2];
                #pragma unroll
                for (int np = 0; np < 2; np++) {
                    uint32_t t4[4];
                    ldsm_x4b(t4, Vs + (np * 16 + brow) * VST + kt32 + kg * 16 + bcol);
                    bv[2 * np][0]     = t4[0];
                    bv[2 * np][1]     = t4[1];
                    bv[2 * np + 1][0] = t4[2];
                    bv[2 * np + 1][1] = t4[3];
                }
                #pragma unroll
                for (int mt = 0; mt < 2; mt++) {
                    float e0 = ex2f(sacc[mt][2 * kg][0]);
                    float e1 = ex2f(sacc[mt][2 * kg][1]);
                    float e2 = ex2f(sacc[mt][2 * kg][2]);
                    float e3 = ex2f(sacc[mt][2 * kg][3]);
                    float e4 = ex2f(sacc[mt][2 * kg + 1][0]);
                    float e5 = ex2f(sacc[mt][2 * kg + 1][1]);
                    float e6 = ex2f(sacc[mt][2 * kg + 1][2]);
                    float e7 = ex2f(sacc[mt][2 * kg + 1][3]);
                    lrun[mt][0] += e0 + e1 + e4 + e5;
                    lrun[mt][1] += e2 + e3 + e6 + e7;
                    uint32_t af[4];
                    af[0] = packbf(e0, e1);
                    af[1] = packbf(e2, e3);
                    af[2] = packbf(e4, e5);
                    af[3] = packbf(e6, e7);
                    #pragma unroll
                    for (int nt = 0; nt < 4; nt++)
                        mma_bf16(oacc[mt][nt], af, bv[nt]);
                }
            }
        }

        #pragma unroll
        for (int mt = 0; mt < 2; mt++) {
            float l0 = lrun[mt][0];
            l0 += __shfl_xor_sync(0xFFFFFFFFu, l0, 1);
            l0 += __shfl_xor_sync(0xFFFFFFFFu, l0, 2);
            float l1 = lrun[mt][1];
            l1 += __shfl_xor_sync(0xFFFFFFFFu, l1, 1);
            l1 += __shfl_xor_sync(0xFFFFFFFFu, l1, 2);
            float inv0 = 1.f / l0, inv1 = 1.f / l1;
            size_t grow = (size_t)seq * S_LEN + qbase + mt * 16 + r;
            #pragma unroll
            for (int nt = 0; nt < 4; nt++) {
                int col = h * DH + nt * 8 + 2 * cc;
                float2 v0, v1;
                v0.x = oacc[mt][nt][0] * inv0; v0.y = oacc[mt][nt][1] * inv0;
                v1.x = oacc[mt][nt][2] * inv1; v1.y = oacc[mt][nt][3] * inv1;
                *(bf162*)(att + grow * C_DIM + col)       = __float22bfloat162_rn(v0);
                *(bf162*)(att + (grow + 8) * C_DIM + col) = __float22bfloat162_rn(v1);
            }
        }
    }
}

__global__ void ln_kernel(const float* __restrict__ vin,
                          const float* __restrict__ g, const float* __restrict__ b,
                          float* __restrict__ out, bf16* __restrict__ outh)
{
    int tx = threadIdx.x, ty = threadIdx.y;
    int row = blockIdx.x * 4 + ty;
    size_t base = (size_t)row * C_DIM + tx * 4;
    float4 v = *(const float4*)(vin + base);
    float s  = v.x + v.y + v.z + v.w;
    float s2 = v.x * v.x + v.y * v.y + v.z * v.z + v.w * v.w;
    #pragma unroll
    for (int off = 16; off; off >>= 1) {
        s  += __shfl_xor_sync(0xFFFFFFFFu, s,  off);
        s2 += __shfl_xor_sync(0xFFFFFFFFu, s2, off);
    }
    __shared__ float red[4][2][2];
    int wh = tx >> 5;
    if ((tx & 31) == 0) { red[ty][wh][0] = s; red[ty][wh][1] = s2; }
    __syncthreads();
    float ts  = red[ty][0][0] + red[ty][1][0];
    float ts2 = red[ty][0][1] + red[ty][1][1];
    float mean = ts * (1.f / C_DIM);
    float var  = ts2 * (1.f / C_DIM) - mean * mean;
    float rstd = rsqrtf(var + EPS);
    float4 gv = *(const float4*)(g + tx * 4);
    float4 bv = *(const float4*)(b + tx * 4);
    float4 o;
    o.x = (v.x - mean) * rstd * gv.x + bv.x;
    o.y = (v.y - mean) * rstd * gv.y + bv.y;
    o.z = (v.z - mean) * rstd * gv.z + bv.z;
    o.w = (v.w - mean) * rstd * gv.w + bv.w;
    *(float4*)(out + base) = o;
    bf162 h0 = __floats2bfloat162_rn(o.x, o.y);
    bf162 h1 = __floats2bfloat162_rn(o.z, o.w);
    uint2 pk;
    pk.x = *(uint32_t*)&h0;
    pk.y = *(uint32_t*)&h1;
    *(uint2*)(outh + base) = pk;
}

__global__ void final_out_kernel(const float* __restrict__ x, float* __restrict__ out)
{
    __shared__ float tile[32][33];
    int t0 = blockIdx.x * 32, c0 = blockIdx.y * 32, b = blockIdx.z;
    int tx = threadIdx.x, ty = threadIdx.y;
    #pragma unroll
    for (int i = ty; i < 32; i += 8) {
        int t = t0 + i;
        size_t row = (size_t)(b * NW + (t >> 7)) * S_LEN + CHUNK + (t & 127);
        tile[i][tx] = x[row * C_DIM + c0 + tx];
    }
    __syncthreads();
    #pragma unroll
    for (int i = ty; i < 32; i += 8)
        out[((size_t)b * C_DIM + c0 + i) * T_LEN + t0 + tx] = tile[tx][i];
}

extern "C" void kernel_launch(void* const* d_in, const int* in_sizes, int n_in,
                              void* d_out, int out_size)
{
    (void)in_sizes; (void)n_in; (void)out_size;
    const float* mem   = (const float*)d_in[0];
    const float* sa_w  = (const float*)d_in[1];
    const float* sa_b  = (const float*)d_in[2];
    const float* sa_ow = (const float*)d_in[3];
    const float* sa_ob = (const float*)d_in[4];
    const float* ca_w  = (const float*)d_in[5];
    const float* ca_b  = (const float*)d_in[6];
    const float* ca_ow = (const float*)d_in[7];
    const float* ca_ob = (const float*)d_in[8];
    const float* w1    = (const float*)d_in[9];
    const float* b1f   = (const float*)d_in[10];
    const float* w2    = (const float*)d_in[11];
    const float* b2f   = (const float*)d_in[12];
    const float* ln_g  = (const float*)d_in[13];
    const float* ln_b  = (const float*)d_in[14];

    float *bufA, *bufB, *proj;
    bf16 *bufAh, *bufBh, *qkv, *att, *h, *wbf;
    cudaGetSymbolAddress((void**)&bufA,  g_bufA);
    cudaGetSymbolAddress((void**)&bufB,  g_bufB);
    cudaGetSymbolAddress((void**)&proj,  g_proj);
    cudaGetSymbolAddress((void**)&bufAh, g_bufAh);
    cudaGetSymbolAddress((void**)&bufBh, g_bufBh);
    cudaGetSymbolAddress((void**)&qkv,   g_qkv);
    cudaGetSymbolAddress((void**)&att,   g_att);
    cudaGetSymbolAddress((void**)&h,     g_h);
    cudaGetSymbolAddress((void**)&wbf,   g_wbf);

    cudaFuncSetAttribute(attn_bf16_kernel, cudaFuncAttributeMaxDynamicSharedMemorySize,
                         ATT_SMEM_BYTES);
    cudaFuncSetAttribute(bgemm_t<0>, cudaFuncAttributeMaxDynamicSharedMemorySize,
                         GEMM_SMEM_BYTES);
    cudaFuncSetAttribute(bgemm_t<1>, cudaFuncAttributeMaxDynamicSharedMemorySize,
                         GEMM_SMEM_BYTES);

    const int MB = M_TOTAL / 128;
    dim3 attn_grid(NSEQ, NHEADS);
    const int BIG = 1 << 20;

    float* LI = bufA;   bf16* LIh = bufAh;
    float* OT = bufB;   bf16* OTh = bufBh;

    convert_w_kernel<<< 384, 256>>>(sa_w, wbf + OFF_SAW, 98304);
    convert_w2_kernel<<<dim3(384, 2), 256>>>(sa_ow, wbf + OFF_SAOW, 32768,
                                             ca_w,  wbf + OFF_CAW,  98304);
    build_x_kernel<<<dim3(12, 8, NSEQ), dim3(32, 8)>>>(mem, bufA, bufAh);

    for (int l = 0; l < NLAYERS; l++) {
        const bf16* w_qkv  = wbf + OFF_SAW  + (size_t)l * 196608;
        const bf16* w_saow = wbf + OFF_SAOW + (size_t)l * 65536;
        const bf16* w_caw  = wbf + OFF_CAW  + (size_t)l * 196608;
        const bf16* w_caow = wbf + OFF_CAOW + (size_t)l * 65536;
        const bf16* w_ff1  = wbf + OFF_W1   + (size_t)l * 262144;
        const bf16* w_ff2  = wbf + OFF_W2   + (size_t)l * 262144;

        bgemm_t<1><<<dim3(768/128, MB), 256, GEMM_SMEM_BYTES>>>(
            LIh, LIh, BIG, C_DIM, w_qkv, C_DIM,
            sa_b + (size_t)l*768, nullptr, qkv, 768, C_DIM, 0);
        attn_bf16_kernel<<<attn_grid, 128, ATT_SMEM_BYTES>>>(qkv, att);

        if (l == 0) {
            convert_w2_kernel<<<dim3(512, 2), 256>>>(ca_ow, wbf + OFF_CAOW, 32768,
                                                     w1,    wbf + OFF_W1,  131072);
            convert_w_kernel<<< 512, 256>>>(w2, wbf + OFF_W2, 131072);
        }

        bgemm_t<0><<<dim3(256/128, MB), 256, GEMM_SMEM_BYTES>>>(
            att, att, BIG, C_DIM, w_saow, C_DIM,
            sa_ob + (size_t)l*256, LI, proj, 256, C_DIM, 0);
        ln_kernel<<<M_TOTAL/4, dim3(64, 4)>>>(proj,
                                              ln_g + (size_t)(l*3 + 0)*C_DIM,
                                              ln_b + (size_t)(l*3 + 0)*C_DIM, OT, OTh);

        bgemm_t<1><<<dim3(768/128, MB), 256, GEMM_SMEM_BYTES>>>(
            OTh, LIh, 2, C_DIM, w_caw, C_DIM,
            ca_b + (size_t)l*768, nullptr, qkv, 768, C_DIM, 0);
        attn_bf16_kernel<<<attn_grid, 128, ATT_SMEM_BYTES>>>(qkv, att);
        bgemm_t<0><<<dim3(256/128, MB), 256, GEMM_SMEM_BYTES>>>(
            att, att, BIG, C_DIM, w_caow, C_DIM,
            ca_ob + (size_t)l*256, OT, proj, 256, C_DIM, 0);
        ln_kernel<<<M_TOTAL/4, dim3(64, 4)>>>(proj,
                                              ln_g + (size_t)(l*3 + 1)*C_DIM,
                                              ln_b + (size_t)(l*3 + 1)*C_DIM, LI, LIh);

        bgemm_t<1><<<dim3(FF_DIM/128, MB), 256, GEMM_SMEM_BYTES>>>(
            LIh, LIh, BIG, C_DIM, w_ff1, C_DIM,
            b1f + (size_t)l*FF_DIM, nullptr, h, FF_DIM, C_DIM, 1);
        bgemm_t<0><<<dim3(256/128, MB), 256, GEMM_SMEM_BYTES>>>(
            h, h, BIG, FF_DIM, w_ff2, FF_DIM,
            b2f + (size_t)l*256, LI, proj, 256, FF_DIM, 0);
        ln_kernel<<<M_TOTAL/4, dim3(64, 4)>>>(proj,
                                              ln_g + (size_t)(l*3 + 2)*C_DIM,
                                              ln_b + (size_t)(l*3 + 2)*C_DIM, OT, OTh);

        float* t0 = LI; LI = OT; OT = t0;
        bf16*  t1 = LIh; LIh = OTh; OTh = t1;
    }

    final_out_kernel<<<dim3(128, 8, 4), dim3(32, 8)>>>(LI, (float*)d_out);
}